// round 5
// baseline (speedup 1.0000x reference)
#include <cuda_runtime.h>
#include <cuda_fp16.h>
#include <mma.h>
#include <cstdint>

using namespace nvcuda;

#define BB    2
#define NTOK  2048
#define DIM   128
#define NH    8
#define DOUT  256
#define BN_   (BB*NTOK)            // 4096
#define FEAT  (NH*DIM)             // 1024
#define SCALE 0.022097086912079608f  // 1/sqrt(2048)
#define LDH   136                  // fp16 tile leading dim
#define LDS4  132                  // fp32 S-tile leading dim

#define ADJ_BLOCKS 512
#define QKV_BLOCKS 1536            // 64 row-tiles x 24 (3 mats x 8 heads)

// ---- scratch (sanctioned __device__ globals) ----
__device__ float g_adjsum[(size_t)BB*NTOK*NTOK];                    // 33.5 MB
__device__ __align__(16) __half g_q[(size_t)NH*BN_*DIM];            // 8.4 MB
__device__ __align__(16) __half g_k[(size_t)NH*BN_*DIM];
__device__ __align__(16) __half g_v[(size_t)NH*BN_*DIM];
__device__ __align__(16) __half g_ocat[(size_t)BN_*FEAT];           // 8.4 MB

// ============================================================
// K1 (MERGED): blocks [0, ADJ_BLOCKS) do adjsum reduce (DRAM-bound, launched
// first); blocks [ADJ_BLOCKS, +QKV_BLOCKS) do q/k/v projections (tensor-bound).
// ============================================================
__global__ void prep_kernel(const float* __restrict__ X,
                            const float4* __restrict__ adj,
                            const float* __restrict__ Wq, const float* __restrict__ bq,
                            const float* __restrict__ Wk, const float* __restrict__ bk,
                            const float* __restrict__ Wv, const float* __restrict__ bv) {
    __shared__ __align__(16) char smem_raw[17408 + 34816];
    const int tid = threadIdx.x;

    if (blockIdx.x < ADJ_BLOCKS) {
        // ---- adjsum: grid-stride over 8.39M float4 ----
        const size_t total = (size_t)BB*NTOK*NTOK;
        for (size_t i = (size_t)blockIdx.x * 256 + tid; i < total;
             i += (size_t)ADJ_BLOCKS * 256) {
            float4 t = adj[i];
            g_adjsum[i] = (t.x + t.y) + (t.z + t.w);
        }
        return;
    }

    // ---- qkv projection ----
    const int id   = blockIdx.x - ADJ_BLOCKS;
    const int row0 = (id & 63) * 64;
    const int z    = id >> 6;                  // 0..23
    const int mat  = z >> 3, h = z & 7;

    __half* sA = (__half*)smem_raw;                       // 64 x 136
    __half* sB = (__half*)(smem_raw + 17408);             // 128 x 136
    float*  sO = (float*)(smem_raw + 17408);              // alias after MMA
    const int warp = tid >> 5;
    const int wr = warp >> 2, wc = warp & 3;

    const float* Wm = (mat == 0 ? Wq : (mat == 1 ? Wk : Wv)) + (size_t)h*DIM*DIM;
    const float* bm = (mat == 0 ? bq : (mat == 1 ? bk : bv)) + (size_t)h*DIM;
    __half* outp = (mat == 0 ? g_q : (mat == 1 ? g_k : g_v)) + (size_t)h*BN_*DIM;

    for (int idx = tid; idx < 64*32; idx += 256) {
        int r = idx >> 5, c = idx & 31;
        float4 t = *(const float4*)(X + (size_t)(row0 + r)*DIM + c*4);
        __half2* d = (__half2*)(sA + r*LDH + c*4);
        d[0] = __floats2half2_rn(t.x, t.y);
        d[1] = __floats2half2_rn(t.z, t.w);
    }
    for (int idx = tid; idx < 128*32; idx += 256) {
        int r = idx >> 5, c = idx & 31;
        float4 t = *(const float4*)(Wm + (size_t)r*DIM + c*4);
        __half2* d = (__half2*)(sB + r*LDH + c*4);
        d[0] = __floats2half2_rn(t.x, t.y);
        d[1] = __floats2half2_rn(t.z, t.w);
    }
    __syncthreads();

    wmma::fragment<wmma::accumulator,16,16,16,float> acc[2][2];
    #pragma unroll
    for (int i = 0; i < 2; i++)
        #pragma unroll
        for (int j = 0; j < 2; j++) wmma::fill_fragment(acc[i][j], 0.0f);

    #pragma unroll
    for (int k = 0; k < 8; k++) {
        wmma::fragment<wmma::matrix_a,16,16,16,__half,wmma::row_major> fa[2];
        wmma::fragment<wmma::matrix_b,16,16,16,__half,wmma::row_major> fb[2];
        #pragma unroll
        for (int i = 0; i < 2; i++)
            wmma::load_matrix_sync(fa[i], sA + (wr*32 + i*16)*LDH + k*16, LDH);
        #pragma unroll
        for (int j = 0; j < 2; j++)
            wmma::load_matrix_sync(fb[j], sB + (k*16)*LDH + wc*32 + j*16, LDH);
        #pragma unroll
        for (int i = 0; i < 2; i++)
            #pragma unroll
            for (int j = 0; j < 2; j++)
                wmma::mma_sync(acc[i][j], fa[i], fb[j], acc[i][j]);
    }
    __syncthreads();
    #pragma unroll
    for (int i = 0; i < 2; i++)
        #pragma unroll
        for (int j = 0; j < 2; j++)
            wmma::store_matrix_sync(sO + (wr*32 + i*16)*LDS4 + wc*32 + j*16,
                                    acc[i][j], LDS4, wmma::mem_row_major);
    __syncthreads();
    for (int idx = tid; idx < 64*128; idx += 256) {
        int r = idx >> 7, e = idx & 127;
        outp[(size_t)(row0 + r)*DIM + e] = __float2half_rn(sO[r*LDS4 + e] + bm[e]);
    }
}

// ============================================================
// K2 (FUSED, fp16 wmma, 512 threads / 16 warps):
//   warp tile 16x64 for both GEMMs; exp: 4 threads per row.
// grid (16,16). smem: Q 34816 | K 34816 | V 34816 | P 34816 | S 67584
// ============================================================
__global__ __launch_bounds__(512, 1) void fused_attn_fp16() {
    extern __shared__ __align__(16) char dsm[];
    __half* sQ = (__half*)dsm;
    __half* sK = (__half*)(dsm + 34816);
    __half* sV = (__half*)(dsm + 2*34816);
    __half* sP = (__half*)(dsm + 3*34816);
    float*  sS = (float*)(dsm + 4*34816);
    __shared__ float sL[128][4];

    const int tid  = threadIdx.x;
    const int warp = tid >> 5;
    const int wr = warp >> 1;           // 0..7: 16-row strip
    const int wc = warp & 1;            // 0..1: 64-col half
    const int n0 = blockIdx.x * 128;
    const int b = blockIdx.y >> 3, h = blockIdx.y & 7;

    const __half* qp  = g_q + (size_t)h*BN_*DIM + (size_t)b*NTOK*DIM;
    const __half* kp  = g_k + (size_t)h*BN_*DIM + (size_t)b*NTOK*DIM;
    const __half* vp  = g_v + (size_t)h*BN_*DIM + (size_t)b*NTOK*DIM;
    const float* adjp = g_adjsum + (size_t)b*NTOK*NTOK;

    // ---- stage Q (raw fp16 copy) ----
    for (int idx = tid; idx < 128*16; idx += 512) {
        int r = idx >> 4, c = idx & 15;
        *(uint4*)(sQ + r*LDH + c*8) = *(const uint4*)(qp + (size_t)(n0 + r)*DIM + c*8);
    }
    __syncthreads();

    wmma::fragment<wmma::accumulator,16,16,16,float> oacc[4];
    #pragma unroll
    for (int j = 0; j < 4; j++) wmma::fill_fragment(oacc[j], 0.0f);

    const int row = tid >> 2;           // 0..127
    const int q4  = tid & 3;            // 32-col quarter
    float lacc = 0.f;

    for (int it = 0; it < 16; it++) {
        const int m0 = it * 128;
        // ---- copy K,V tiles (raw fp16) ----
        for (int idx = tid; idx < 128*16; idx += 512) {
            int r = idx >> 4, c = idx & 15;
            *(uint4*)(sK + r*LDH + c*8) = *(const uint4*)(kp + (size_t)(m0 + r)*DIM + c*8);
            *(uint4*)(sV + r*LDH + c*8) = *(const uint4*)(vp + (size_t)(m0 + r)*DIM + c*8);
        }
        __syncthreads();

        // ---- S = Q K^T : warp computes 16x64 strip ----
        {
            wmma::fragment<wmma::accumulator,16,16,16,float> sacc[4];
            #pragma unroll
            for (int j = 0; j < 4; j++) wmma::fill_fragment(sacc[j], 0.0f);
            #pragma unroll
            for (int k = 0; k < 8; k++) {
                wmma::fragment<wmma::matrix_a,16,16,16,__half,wmma::row_major> aQ;
                wmma::load_matrix_sync(aQ, sQ + (wr*16)*LDH + k*16, LDH);
                #pragma unroll
                for (int j = 0; j < 4; j++) {
                    wmma::fragment<wmma::matrix_b,16,16,16,__half,wmma::col_major> bK;
                    wmma::load_matrix_sync(bK, sK + (wc*64 + j*16)*LDH + k*16, LDH);
                    wmma::mma_sync(sacc[j], aQ, bK, sacc[j]);
                }
            }
            #pragma unroll
            for (int j = 0; j < 4; j++)
                wmma::store_matrix_sync(sS + (wr*16)*LDS4 + wc*64 + j*16, sacc[j],
                                        LDS4, wmma::mem_row_major);
        }
        __syncthreads();

        // ---- P = exp(S*SCALE*adj) -> fp16, accumulate row-sum ----
        {
            const float* srow = sS + row*LDS4 + q4*32;
            const float* arow = adjp + (size_t)(n0 + row)*NTOK + m0 + q4*32;
            __half2* prow = (__half2*)(sP + row*LDH + q4*32);
            float4 a4[8];
            #pragma unroll
            for (int g = 0; g < 8; g++) a4[g] = *(const float4*)(arow + g*4);
            float lsum = 0.f;
            #pragma unroll
            for (int g = 0; g < 8; g++) {
                float e0 = __expf(srow[g*4+0] * SCALE * a4[g].x);
                float e1 = __expf(srow[g*4+1] * SCALE * a4[g].y);
                float e2 = __expf(srow[g*4+2] * SCALE * a4[g].z);
                float e3 = __expf(srow[g*4+3] * SCALE * a4[g].w);
                lsum += (e0 + e1) + (e2 + e3);
                prow[g*2]     = __floats2half2_rn(e0, e1);
                prow[g*2 + 1] = __floats2half2_rn(e2, e3);
            }
            lacc += lsum;
        }
        __syncthreads();

        // ---- O += P @ V : warp 16x64 strip ----
        #pragma unroll
        for (int k = 0; k < 8; k++) {
            wmma::fragment<wmma::matrix_a,16,16,16,__half,wmma::row_major> aP;
            wmma::load_matrix_sync(aP, sP + (wr*16)*LDH + k*16, LDH);
            #pragma unroll
            for (int j = 0; j < 4; j++) {
                wmma::fragment<wmma::matrix_b,16,16,16,__half,wmma::row_major> bV;
                wmma::load_matrix_sync(bV, sV + (k*16)*LDH + wc*64 + j*16, LDH);
                wmma::mma_sync(oacc[j], aP, bV, oacc[j]);
            }
        }
        __syncthreads();   // before next iter overwrites sK/sV/sP/sS
    }

    // ---- epilogue: O / l -> g_ocat (fp16) ----
    sL[row][q4] = lacc;
    #pragma unroll
    for (int j = 0; j < 4; j++)
        wmma::store_matrix_sync(sS + (wr*16)*LDS4 + wc*64 + j*16, oacc[j],
                                LDS4, wmma::mem_row_major);
    __syncthreads();
    {
        const float linv = 1.0f / ((sL[row][0] + sL[row][1])
                                 + (sL[row][2] + sL[row][3]));
        const float* orow = sS + row*LDS4 + q4*32;
        __half2* drow = (__half2*)(g_ocat + (size_t)(b*NTOK + n0 + row)*FEAT
                                   + h*DIM + q4*32);
        #pragma unroll
        for (int c = 0; c < 16; c++)
            drow[c] = __floats2half2_rn(orow[2*c] * linv, orow[2*c+1] * linv);
    }
}

// ============================================================
// K3: out = ocat[4096,1024] @ Wout[1024,256] + bout  (single kernel)
// grid (64, 8): 512 CTAs, 64x32 tiles, full K. block 128 (4 warps, 32x16 each)
// ============================================================
__global__ void outproj_kernel(const float* __restrict__ Wout,
                               const float* __restrict__ bout,
                               float* __restrict__ out) {
    __shared__ __align__(16) char sm[9216 + 5120];
    __half* sA = (__half*)sm;             // 64 x 72
    __half* sB = (__half*)(sm + 9216);    // 64 x 40
    float*  sO = (float*)sm;              // 64 x 36 (alias after MMA)
    const int tid  = threadIdx.x;
    const int warp = tid >> 5;
    const int wr = warp >> 1, wc = warp & 1;
    const int r0 = blockIdx.x * 64, c0 = blockIdx.y * 32;

    wmma::fragment<wmma::accumulator,16,16,16,float> acc[2];
    #pragma unroll
    for (int i = 0; i < 2; i++) wmma::fill_fragment(acc[i], 0.0f);

    for (int kb = 0; kb < FEAT; kb += 64) {
        // sA: ocat fp16 raw copy (64 x 64)
        for (int idx = tid; idx < 64*8; idx += 128) {
            int r = idx >> 3, c = idx & 7;
            *(uint4*)(sA + r*72 + c*8) =
                *(const uint4*)(g_ocat + (size_t)(r0 + r)*FEAT + kb + c*8);
        }
        // sB: Wout fp32 -> fp16 (64 x 32)
        for (int idx = tid; idx < 64*8; idx += 128) {
            int r = idx >> 3, c4 = idx & 7;
            float4 t = *(const float4*)(Wout + (size_t)(kb + r)*DOUT + c0 + c4*4);
            __half2* d = (__half2*)(sB + r*40 + c4*4);
            d[0] = __floats2half2_rn(t.x, t.y);
            d[1] = __floats2half2_rn(t.z, t.w);
        }
        __syncthreads();
        #pragma unroll
        for (int kk = 0; kk < 4; kk++) {
            wmma::fragment<wmma::matrix_a,16,16,16,__half,wmma::row_major> fa[2];
            wmma::fragment<wmma::matrix_b,16,16,16,__half,wmma::row_major> fb;
            #pragma unroll
            for (int i = 0; i < 2; i++)
                wmma::load_matrix_sync(fa[i], sA + (wr*32 + i*16)*72 + kk*16, 72);
            wmma::load_matrix_sync(fb, sB + (kk*16)*40 + wc*16, 40);
            #pragma unroll
            for (int i = 0; i < 2; i++)
                wmma::mma_sync(acc[i], fa[i], fb, acc[i]);
        }
        __syncthreads();
    }
    #pragma unroll
    for (int i = 0; i < 2; i++)
        wmma::store_matrix_sync(sO + (wr*32 + i*16)*36 + wc*16, acc[i],
                                36, wmma::mem_row_major);
    __syncthreads();
    for (int idx = tid; idx < 64*32; idx += 128) {
        int r = idx >> 5, c = idx & 31;
        out[(size_t)(r0 + r)*DOUT + c0 + c] = sO[r*36 + c] + bout[c0 + c];
    }
}

// ============================================================
extern "C" void kernel_launch(void* const* d_in, const int* in_sizes, int n_in,
                              void* d_out, int out_size) {
    const float* X    = (const float*)d_in[0];
    const float* adj  = (const float*)d_in[1];
    const float* Wq   = (const float*)d_in[2];
    const float* bq   = (const float*)d_in[3];
    const float* Wk   = (const float*)d_in[4];
    const float* bk   = (const float*)d_in[5];
    const float* Wv   = (const float*)d_in[6];
    const float* bv   = (const float*)d_in[7];
    const float* Wout = (const float*)d_in[8];
    const float* bout = (const float*)d_in[9];
    float* out = (float*)d_out;

    const int fused_smem = 4*34816 + 67584;   // 206,848 B
    cudaFuncSetAttribute(fused_attn_fp16,
                         cudaFuncAttributeMaxDynamicSharedMemorySize, fused_smem);

    prep_kernel<<<ADJ_BLOCKS + QKV_BLOCKS, 256>>>((const float*)X, (const float4*)adj,
                                                  Wq, bq, Wk, bk, Wv, bv);
    fused_attn_fp16<<<dim3(NTOK/128, BB*NH), 512, fused_smem>>>();
    outproj_kernel<<<dim3(BN_/64, DOUT/32), 128>>>(Wout, bout, out);
}

// round 6
// speedup vs baseline: 1.0773x; 1.0773x over previous
#include <cuda_runtime.h>
#include <cuda_fp16.h>
#include <mma.h>
#include <cstdint>

using namespace nvcuda;

#define BB    2
#define NTOK  2048
#define DIM   128
#define NH    8
#define DOUT  256
#define BN_   (BB*NTOK)            // 4096
#define FEAT  (NH*DIM)             // 1024
#define SCALE 0.022097086912079608f  // 1/sqrt(2048)
#define LDH   136                  // fp16 tile leading dim
#define LDS4  132                  // fp32 S-tile leading dim

// ---- scratch (sanctioned __device__ globals) ----
__device__ float g_adjsum[(size_t)BB*NTOK*NTOK];                    // 33.5 MB
__device__ __align__(16) __half g_q[(size_t)NH*BN_*DIM];            // 8.4 MB
__device__ __align__(16) __half g_k[(size_t)NH*BN_*DIM];
__device__ __align__(16) __half g_v[(size_t)NH*BN_*DIM];
__device__ __align__(16) __half g_ocat[(size_t)BN_*FEAT];           // 8.4 MB

// ============================================================
// K1: adjsum[b,n,m] = sum_w nodeadj[b,n,m,w]
// ============================================================
__global__ void adjsum_kernel(const float4* __restrict__ adj) {
    size_t i = (size_t)blockIdx.x * blockDim.x + threadIdx.x;
    if (i < (size_t)BB*NTOK*NTOK) {
        float4 t = adj[i];
        g_adjsum[i] = (t.x + t.y) + (t.z + t.w);
    }
}

// ============================================================
// K2: q/k/v[h] = fp16( X @ W[h] + b[h] )
// grid (BN_/64, 3*NH), block 256 (8 warps: 2x4, each 32x32)
// ============================================================
__global__ void qkv_kernel(const float* __restrict__ X,
                           const float* __restrict__ Wq, const float* __restrict__ bq,
                           const float* __restrict__ Wk, const float* __restrict__ bk,
                           const float* __restrict__ Wv, const float* __restrict__ bv) {
    __shared__ __align__(16) char smem_raw[17408 + 34816];   // sA 64x136 h | sB 128x136 h
    __half* sA = (__half*)smem_raw;
    __half* sB = (__half*)(smem_raw + 17408);
    float*  sO = (float*)(smem_raw + 17408);    // alias sB after MMA (64x132 f32)
    const int tid  = threadIdx.x;
    const int warp = tid >> 5;
    const int wr = warp >> 2, wc = warp & 3;
    const int row0 = blockIdx.x * 64;
    const int z = blockIdx.y;
    const int mat = z >> 3, h = z & 7;

    const float* Wm = (mat == 0 ? Wq : (mat == 1 ? Wk : Wv)) + (size_t)h*DIM*DIM;
    const float* bm = (mat == 0 ? bq : (mat == 1 ? bk : bv)) + (size_t)h*DIM;
    __half* outp = (mat == 0 ? g_q : (mat == 1 ? g_k : g_v)) + (size_t)h*BN_*DIM;

    // stage X tile (fp32 -> fp16)
    for (int idx = tid; idx < 64*32; idx += 256) {
        int r = idx >> 5, c = idx & 31;
        float4 t = *(const float4*)(X + (size_t)(row0 + r)*DIM + c*4);
        __half2* d = (__half2*)(sA + r*LDH + c*4);
        d[0] = __floats2half2_rn(t.x, t.y);
        d[1] = __floats2half2_rn(t.z, t.w);
    }
    // stage W (fp32 -> fp16), full 128x128
    for (int idx = tid; idx < 128*32; idx += 256) {
        int r = idx >> 5, c = idx & 31;
        float4 t = *(const float4*)(Wm + (size_t)r*DIM + c*4);
        __half2* d = (__half2*)(sB + r*LDH + c*4);
        d[0] = __floats2half2_rn(t.x, t.y);
        d[1] = __floats2half2_rn(t.z, t.w);
    }
    __syncthreads();

    wmma::fragment<wmma::accumulator,16,16,16,float> acc[2][2];
    #pragma unroll
    for (int i = 0; i < 2; i++)
        #pragma unroll
        for (int j = 0; j < 2; j++) wmma::fill_fragment(acc[i][j], 0.0f);

    #pragma unroll
    for (int k = 0; k < 8; k++) {
        wmma::fragment<wmma::matrix_a,16,16,16,__half,wmma::row_major> fa[2];
        wmma::fragment<wmma::matrix_b,16,16,16,__half,wmma::row_major> fb[2];
        #pragma unroll
        for (int i = 0; i < 2; i++)
            wmma::load_matrix_sync(fa[i], sA + (wr*32 + i*16)*LDH + k*16, LDH);
        #pragma unroll
        for (int j = 0; j < 2; j++)
            wmma::load_matrix_sync(fb[j], sB + (k*16)*LDH + wc*32 + j*16, LDH);
        #pragma unroll
        for (int i = 0; i < 2; i++)
            #pragma unroll
            for (int j = 0; j < 2; j++)
                wmma::mma_sync(acc[i][j], fa[i], fb[j], acc[i][j]);
    }
    __syncthreads();   // done reading sB before aliasing as sO
    #pragma unroll
    for (int i = 0; i < 2; i++)
        #pragma unroll
        for (int j = 0; j < 2; j++)
            wmma::store_matrix_sync(sO + (wr*32 + i*16)*LDS4 + wc*32 + j*16,
                                    acc[i][j], LDS4, wmma::mem_row_major);
    __syncthreads();
    for (int idx = tid; idx < 64*128; idx += 256) {
        int r = idx >> 7, e = idx & 127;
        outp[(size_t)(row0 + r)*DIM + e] = __float2half_rn(sO[r*LDS4 + e] + bm[e]);
    }
}

// ============================================================
// K3 (FUSED, fp16 wmma, 256 threads / 8 warps — R4 proven shape):
//   S = Q K^T (fp32 acc) ; P = fp16(exp(S*SCALE*adj)) ; O += P V ; O/l -> g_ocat
// grid (16,16). smem: Q 34816 | K 34816 | V 34816 | P 34816 | S 67584
// ============================================================
__global__ __launch_bounds__(256, 1) void fused_attn_fp16() {
    extern __shared__ __align__(16) char dsm[];
    __half* sQ = (__half*)dsm;
    __half* sK = (__half*)(dsm + 34816);
    __half* sV = (__half*)(dsm + 2*34816);
    __half* sP = (__half*)(dsm + 3*34816);
    float*  sS = (float*)(dsm + 4*34816);
    __shared__ float sL[128][2];

    const int tid  = threadIdx.x;
    const int warp = tid >> 5;
    const int n0 = blockIdx.x * 128;
    const int b = blockIdx.y >> 3, h = blockIdx.y & 7;

    const __half* qp  = g_q + (size_t)h*BN_*DIM + (size_t)b*NTOK*DIM;
    const __half* kp  = g_k + (size_t)h*BN_*DIM + (size_t)b*NTOK*DIM;
    const __half* vp  = g_v + (size_t)h*BN_*DIM + (size_t)b*NTOK*DIM;
    const float* adjp = g_adjsum + (size_t)b*NTOK*NTOK;

    // ---- stage Q (raw fp16 copy, 128 rows x 16 uint4) ----
    for (int idx = tid; idx < 128*16; idx += 256) {
        int r = idx >> 4, c = idx & 15;
        *(uint4*)(sQ + r*LDH + c*8) = *(const uint4*)(qp + (size_t)(n0 + r)*DIM + c*8);
    }
    __syncthreads();

    wmma::fragment<wmma::accumulator,16,16,16,float> oacc[8];
    #pragma unroll
    for (int j = 0; j < 8; j++) wmma::fill_fragment(oacc[j], 0.0f);

    const int row  = tid >> 1;          // 0..127 (exp/epilogue row)
    const int half = tid & 1;           // 64-col half
    float lacc = 0.f;

    for (int it = 0; it < 16; it++) {
        const int m0 = it * 128;
        // ---- copy K,V tiles (raw fp16) ----
        for (int idx = tid; idx < 128*16; idx += 256) {
            int r = idx >> 4, c = idx & 15;
            *(uint4*)(sK + r*LDH + c*8) = *(const uint4*)(kp + (size_t)(m0 + r)*DIM + c*8);
            *(uint4*)(sV + r*LDH + c*8) = *(const uint4*)(vp + (size_t)(m0 + r)*DIM + c*8);
        }
        __syncthreads();

        // ---- S = Q K^T : warp computes 16x128 strip ----
        {
            wmma::fragment<wmma::accumulator,16,16,16,float> sacc[8];
            #pragma unroll
            for (int j = 0; j < 8; j++) wmma::fill_fragment(sacc[j], 0.0f);
            #pragma unroll
            for (int k = 0; k < 8; k++) {
                wmma::fragment<wmma::matrix_a,16,16,16,__half,wmma::row_major> aQ;
                wmma::load_matrix_sync(aQ, sQ + (warp*16)*LDH + k*16, LDH);
                #pragma unroll
                for (int j = 0; j < 8; j++) {
                    wmma::fragment<wmma::matrix_b,16,16,16,__half,wmma::col_major> bK;
                    wmma::load_matrix_sync(bK, sK + (j*16)*LDH + k*16, LDH);
                    wmma::mma_sync(sacc[j], aQ, bK, sacc[j]);
                }
            }
            #pragma unroll
            for (int j = 0; j < 8; j++)
                wmma::store_matrix_sync(sS + (warp*16)*LDS4 + j*16, sacc[j],
                                        LDS4, wmma::mem_row_major);
        }
        __syncthreads();

        // ---- P = exp(S*SCALE*adj) -> fp16, accumulate row-sum ----
        {
            const float* srow = sS + row*LDS4 + half*64;
            const float* arow = adjp + (size_t)(n0 + row)*NTOK + m0 + half*64;
            __half2* prow = (__half2*)(sP + row*LDH + half*64);
            float lsum = 0.f;
            #pragma unroll
            for (int c = 0; c < 64; c += 4) {
                float4 a4 = *(const float4*)(arow + c);
                float e0 = __expf(srow[c+0] * SCALE * a4.x);
                float e1 = __expf(srow[c+1] * SCALE * a4.y);
                float e2 = __expf(srow[c+2] * SCALE * a4.z);
                float e3 = __expf(srow[c+3] * SCALE * a4.w);
                lsum += (e0 + e1) + (e2 + e3);
                prow[c/2]     = __floats2half2_rn(e0, e1);
                prow[c/2 + 1] = __floats2half2_rn(e2, e3);
            }
            lacc += lsum;
        }
        __syncthreads();

        // ---- O += P @ V ----
        #pragma unroll
        for (int k = 0; k < 8; k++) {
            wmma::fragment<wmma::matrix_a,16,16,16,__half,wmma::row_major> aP;
            wmma::load_matrix_sync(aP, sP + (warp*16)*LDH + k*16, LDH);
            #pragma unroll
            for (int j = 0; j < 8; j++) {
                wmma::fragment<wmma::matrix_b,16,16,16,__half,wmma::row_major> bV;
                wmma::load_matrix_sync(bV, sV + (k*16)*LDH + j*16, LDH);
                wmma::mma_sync(oacc[j], aP, bV, oacc[j]);
            }
        }
        __syncthreads();   // before next iter overwrites sK/sV/sP (and sS)
    }

    // ---- epilogue: O / l -> g_ocat (fp16) ----
    sL[row][half] = lacc;
    #pragma unroll
    for (int j = 0; j < 8; j++)
        wmma::store_matrix_sync(sS + (warp*16)*LDS4 + j*16, oacc[j],
                                LDS4, wmma::mem_row_major);
    __syncthreads();
    {
        const float linv = 1.0f / (sL[row][0] + sL[row][1]);
        const float* orow = sS + row*LDS4 + half*64;
        __half2* drow = (__half2*)(g_ocat + (size_t)(b*NTOK + n0 + row)*FEAT
                                   + h*DIM + half*64);
        #pragma unroll
        for (int c = 0; c < 32; c++)
            drow[c] = __floats2half2_rn(orow[2*c] * linv, orow[2*c+1] * linv);
    }
}

// ============================================================
// K4: out = ocat[4096,1024] @ Wout[1024,256] + bout  (single kernel)
// grid (64, 8): 512 CTAs, 64x32 tiles, full K. block 128 (4 warps, 32x16 each)
// ============================================================
__global__ void outproj_kernel(const float* __restrict__ Wout,
                               const float* __restrict__ bout,
                               float* __restrict__ out) {
    __shared__ __align__(16) char sm[9216 + 5120];
    __half* sA = (__half*)sm;             // 64 x 72
    __half* sB = (__half*)(sm + 9216);    // 64 x 40
    float*  sO = (float*)sm;              // 64 x 36 (alias after MMA)
    const int tid  = threadIdx.x;
    const int warp = tid >> 5;
    const int wr = warp >> 1, wc = warp & 1;
    const int r0 = blockIdx.x * 64, c0 = blockIdx.y * 32;

    wmma::fragment<wmma::accumulator,16,16,16,float> acc[2];
    #pragma unroll
    for (int i = 0; i < 2; i++) wmma::fill_fragment(acc[i], 0.0f);

    for (int kb = 0; kb < FEAT; kb += 64) {
        // sA: ocat fp16 raw copy (64 x 64)
        for (int idx = tid; idx < 64*8; idx += 128) {
            int r = idx >> 3, c = idx & 7;
            *(uint4*)(sA + r*72 + c*8) =
                *(const uint4*)(g_ocat + (size_t)(r0 + r)*FEAT + kb + c*8);
        }
        // sB: Wout fp32 -> fp16 (64 x 32)
        for (int idx = tid; idx < 64*8; idx += 128) {
            int r = idx >> 3, c4 = idx & 7;
            float4 t = *(const float4*)(Wout + (size_t)(kb + r)*DOUT + c0 + c4*4);
            __half2* d = (__half2*)(sB + r*40 + c4*4);
            d[0] = __floats2half2_rn(t.x, t.y);
            d[1] = __floats2half2_rn(t.z, t.w);
        }
        __syncthreads();
        #pragma unroll
        for (int kk = 0; kk < 4; kk++) {
            wmma::fragment<wmma::matrix_a,16,16,16,__half,wmma::row_major> fa[2];
            wmma::fragment<wmma::matrix_b,16,16,16,__half,wmma::row_major> fb;
            #pragma unroll
            for (int i = 0; i < 2; i++)
                wmma::load_matrix_sync(fa[i], sA + (wr*32 + i*16)*72 + kk*16, 72);
            wmma::load_matrix_sync(fb, sB + (kk*16)*40 + wc*16, 40);
            #pragma unroll
            for (int i = 0; i < 2; i++)
                wmma::mma_sync(acc[i], fa[i], fb, acc[i]);
        }
        __syncthreads();
    }
    #pragma unroll
    for (int i = 0; i < 2; i++)
        wmma::store_matrix_sync(sO + (wr*32 + i*16)*36 + wc*16, acc[i],
                                36, wmma::mem_row_major);
    __syncthreads();
    for (int idx = tid; idx < 64*32; idx += 128) {
        int r = idx >> 5, c = idx & 31;
        out[(size_t)(r0 + r)*DOUT + c0 + c] = sO[r*36 + c] + bout[c0 + c];
    }
}

// ============================================================
extern "C" void kernel_launch(void* const* d_in, const int* in_sizes, int n_in,
                              void* d_out, int out_size) {
    const float* X    = (const float*)d_in[0];
    const float* adj  = (const float*)d_in[1];
    const float* Wq   = (const float*)d_in[2];
    const float* bq   = (const float*)d_in[3];
    const float* Wk   = (const float*)d_in[4];
    const float* bk   = (const float*)d_in[5];
    const float* Wv   = (const float*)d_in[6];
    const float* bv   = (const float*)d_in[7];
    const float* Wout = (const float*)d_in[8];
    const float* bout = (const float*)d_in[9];
    float* out = (float*)d_out;

    const int fused_smem = 4*34816 + 67584;   // 206,848 B
    cudaFuncSetAttribute(fused_attn_fp16,
                         cudaFuncAttributeMaxDynamicSharedMemorySize, fused_smem);

    {
        size_t total = (size_t)BB*NTOK*NTOK;
        adjsum_kernel<<<(unsigned)((total + 255) / 256), 256>>>((const float4*)adj);
    }
    qkv_kernel<<<dim3(BN_/64, 3*NH), 256>>>(X, Wq, bq, Wk, bk, Wv, bv);
    fused_attn_fp16<<<dim3(NTOK/128, BB*NH), 256, fused_smem>>>();
    outproj_kernel<<<dim3(BN_/64, DOUT/32), 128>>>(Wout, bout, out);
}

// round 7
// speedup vs baseline: 1.2331x; 1.1446x over previous
#include <cuda_runtime.h>
#include <cuda_fp16.h>
#include <mma.h>
#include <cstdint>

using namespace nvcuda;

#define BB    2
#define NTOK  2048
#define DIM   128
#define NH    8
#define DOUT  256
#define BN_   (BB*NTOK)            // 4096
#define FEAT  (NH*DIM)             // 1024
#define SCALE 0.022097086912079608f  // 1/sqrt(2048)
#define LDH   136                  // fp16 tile leading dim (272 B rows)
#define LDS4  132                  // fp32 S-tile leading dim (528 B rows)

// ---- scratch (sanctioned __device__ globals) ----
__device__ float g_adjsum[(size_t)BB*NTOK*NTOK];                    // 33.5 MB
__device__ __align__(16) __half g_q[(size_t)NH*BN_*DIM];            // 8.4 MB
__device__ __align__(16) __half g_k[(size_t)NH*BN_*DIM];
__device__ __align__(16) __half g_v[(size_t)NH*BN_*DIM];
__device__ __align__(16) __half g_ocat[(size_t)BN_*FEAT];           // 8.4 MB
__device__ float g_psum[4][(size_t)BN_*DOUT];                       // 16.8 MB

// ---- cp.async helpers ----
__device__ __forceinline__ void cp16(uint32_t saddr, const void* gptr) {
    asm volatile("cp.async.cg.shared.global [%0], [%1], 16;"
                 :: "r"(saddr), "l"(gptr));
}
#define CP_COMMIT() asm volatile("cp.async.commit_group;" ::: "memory")
#define CP_WAIT1()  asm volatile("cp.async.wait_group 1;" ::: "memory")
#define CP_WAIT0()  asm volatile("cp.async.wait_group 0;" ::: "memory")

// ============================================================
// K1: adjsum[b,n,m] = sum_w nodeadj[b,n,m,w]
// ============================================================
__global__ void adjsum_kernel(const float4* __restrict__ adj) {
    size_t i = (size_t)blockIdx.x * blockDim.x + threadIdx.x;
    if (i < (size_t)BB*NTOK*NTOK) {
        float4 t = adj[i];
        g_adjsum[i] = (t.x + t.y) + (t.z + t.w);
    }
}

// ============================================================
// K2: q/k/v[h] = fp16( X @ W[h] + b[h] )
// grid (BN_/64, 3*NH), block 256 (8 warps: 2x4, each 32x32)
// ============================================================
__global__ void qkv_kernel(const float* __restrict__ X,
                           const float* __restrict__ Wq, const float* __restrict__ bq,
                           const float* __restrict__ Wk, const float* __restrict__ bk,
                           const float* __restrict__ Wv, const float* __restrict__ bv) {
    __shared__ __align__(16) char smem_raw[17408 + 34816];
    __half* sA = (__half*)smem_raw;
    __half* sB = (__half*)(smem_raw + 17408);
    float*  sO = (float*)(smem_raw + 17408);
    const int tid  = threadIdx.x;
    const int warp = tid >> 5;
    const int wr = warp >> 2, wc = warp & 3;
    const int row0 = blockIdx.x * 64;
    const int z = blockIdx.y;
    const int mat = z >> 3, h = z & 7;

    const float* Wm = (mat == 0 ? Wq : (mat == 1 ? Wk : Wv)) + (size_t)h*DIM*DIM;
    const float* bm = (mat == 0 ? bq : (mat == 1 ? bk : bv)) + (size_t)h*DIM;
    __half* outp = (mat == 0 ? g_q : (mat == 1 ? g_k : g_v)) + (size_t)h*BN_*DIM;

    for (int idx = tid; idx < 64*32; idx += 256) {
        int r = idx >> 5, c = idx & 31;
        float4 t = *(const float4*)(X + (size_t)(row0 + r)*DIM + c*4);
        __half2* d = (__half2*)(sA + r*LDH + c*4);
        d[0] = __floats2half2_rn(t.x, t.y);
        d[1] = __floats2half2_rn(t.z, t.w);
    }
    for (int idx = tid; idx < 128*32; idx += 256) {
        int r = idx >> 5, c = idx & 31;
        float4 t = *(const float4*)(Wm + (size_t)r*DIM + c*4);
        __half2* d = (__half2*)(sB + r*LDH + c*4);
        d[0] = __floats2half2_rn(t.x, t.y);
        d[1] = __floats2half2_rn(t.z, t.w);
    }
    __syncthreads();

    wmma::fragment<wmma::accumulator,16,16,16,float> acc[2][2];
    #pragma unroll
    for (int i = 0; i < 2; i++)
        #pragma unroll
        for (int j = 0; j < 2; j++) wmma::fill_fragment(acc[i][j], 0.0f);

    #pragma unroll
    for (int k = 0; k < 8; k++) {
        wmma::fragment<wmma::matrix_a,16,16,16,__half,wmma::row_major> fa[2];
        wmma::fragment<wmma::matrix_b,16,16,16,__half,wmma::row_major> fb[2];
        #pragma unroll
        for (int i = 0; i < 2; i++)
            wmma::load_matrix_sync(fa[i], sA + (wr*32 + i*16)*LDH + k*16, LDH);
        #pragma unroll
        for (int j = 0; j < 2; j++)
            wmma::load_matrix_sync(fb[j], sB + (k*16)*LDH + wc*32 + j*16, LDH);
        #pragma unroll
        for (int i = 0; i < 2; i++)
            #pragma unroll
            for (int j = 0; j < 2; j++)
                wmma::mma_sync(acc[i][j], fa[i], fb[j], acc[i][j]);
    }
    __syncthreads();
    #pragma unroll
    for (int i = 0; i < 2; i++)
        #pragma unroll
        for (int j = 0; j < 2; j++)
            wmma::store_matrix_sync(sO + (wr*32 + i*16)*LDS4 + wc*32 + j*16,
                                    acc[i][j], LDS4, wmma::mem_row_major);
    __syncthreads();
    for (int idx = tid; idx < 64*128; idx += 256) {
        int r = idx >> 7, e = idx & 127;
        outp[(size_t)(row0 + r)*DIM + e] = __float2half_rn(sO[r*LDS4 + e] + bm[e]);
    }
}

// ============================================================
// K3 (FUSED, fp16 wmma, cp.async pipelined):
//   S = Q K^T ; P = fp16(exp(S*SCALE*adj)) [P aliases S] ; O += P V ; O/l
// grid (16,16), 256 threads (8 warps x 16x128 strips)
// smem: Q 34816 | K 34816 | V 34816 | S/P 67584 = 172,032 B
// ============================================================
__global__ __launch_bounds__(256, 1) void fused_attn_fp16() {
    extern __shared__ __align__(16) char dsm[];
    __half* sQ = (__half*)dsm;
    __half* sK = (__half*)(dsm + 34816);
    __half* sV = (__half*)(dsm + 2*34816);
    float*  sS = (float*)(dsm + 3*34816);
    __half* sP = (__half*)(dsm + 3*34816);   // aliases sS (disjoint lifetimes)
    __shared__ float sL[128][2];

    const int tid  = threadIdx.x;
    const int warp = tid >> 5;
    const int n0 = blockIdx.x * 128;
    const int b = blockIdx.y >> 3, h = blockIdx.y & 7;

    const __half* qp  = g_q + (size_t)h*BN_*DIM + (size_t)b*NTOK*DIM;
    const __half* kp  = g_k + (size_t)h*BN_*DIM + (size_t)b*NTOK*DIM;
    const __half* vp  = g_v + (size_t)h*BN_*DIM + (size_t)b*NTOK*DIM;
    const float* adjp = g_adjsum + (size_t)b*NTOK*NTOK;

    const uint32_t uK = (uint32_t)__cvta_generic_to_shared(sK);
    const uint32_t uV = (uint32_t)__cvta_generic_to_shared(sV);

    // ---- prologue: async K[0], V[0]; stage Q via regular copy ----
    for (int idx = tid; idx < 128*16; idx += 256) {
        int r = idx >> 4, c = idx & 15;
        cp16(uK + r*272 + c*16, kp + (size_t)r*DIM + c*8);
    }
    CP_COMMIT();
    for (int idx = tid; idx < 128*16; idx += 256) {
        int r = idx >> 4, c = idx & 15;
        cp16(uV + r*272 + c*16, vp + (size_t)r*DIM + c*8);
    }
    CP_COMMIT();
    for (int idx = tid; idx < 128*16; idx += 256) {
        int r = idx >> 4, c = idx & 15;
        *(uint4*)(sQ + r*LDH + c*8) = *(const uint4*)(qp + (size_t)(n0 + r)*DIM + c*8);
    }

    wmma::fragment<wmma::accumulator,16,16,16,float> oacc[8];
    #pragma unroll
    for (int j = 0; j < 8; j++) wmma::fill_fragment(oacc[j], 0.0f);

    const int row  = tid >> 1;
    const int half = tid & 1;
    float lacc = 0.f;

    for (int it = 0; it < 16; it++) {
        const int m0 = it * 128;
        CP_WAIT1();
        __syncthreads();                    // sK[it] (and Q on it=0) visible

        // ---- S = Q K^T : warp computes 16x128 strip ----
        {
            wmma::fragment<wmma::accumulator,16,16,16,float> sacc[8];
            #pragma unroll
            for (int j = 0; j < 8; j++) wmma::fill_fragment(sacc[j], 0.0f);
            #pragma unroll
            for (int k = 0; k < 8; k++) {
                wmma::fragment<wmma::matrix_a,16,16,16,__half,wmma::row_major> aQ;
                wmma::load_matrix_sync(aQ, sQ + (warp*16)*LDH + k*16, LDH);
                #pragma unroll
                for (int j = 0; j < 8; j++) {
                    wmma::fragment<wmma::matrix_b,16,16,16,__half,wmma::col_major> bK;
                    wmma::load_matrix_sync(bK, sK + (j*16)*LDH + k*16, LDH);
                    wmma::mma_sync(sacc[j], aQ, bK, sacc[j]);
                }
            }
            #pragma unroll
            for (int j = 0; j < 8; j++)
                wmma::store_matrix_sync(sS + (warp*16)*LDS4 + j*16, sacc[j],
                                        LDS4, wmma::mem_row_major);
        }
        __syncthreads();                    // sS visible; sK free

        // ---- prefetch K[it+1] (hidden behind exp + PV) ----
        if (it < 15) {
            const __half* kn = kp + (size_t)(m0 + 128)*DIM;
            for (int idx = tid; idx < 128*16; idx += 256) {
                int r = idx >> 4, c = idx & 15;
                cp16(uK + r*272 + c*16, kn + (size_t)r*DIM + c*8);
            }
            CP_COMMIT();
        }

        // ---- exp: read S -> regs, sync, write P (aliased on S) ----
        {
            const float* srow = sS + row*LDS4 + half*64;
            const float* arow = adjp + (size_t)(n0 + row)*NTOK + m0 + half*64;
            uint32_t pst[32];
            float lsum = 0.f;
            #pragma unroll
            for (int c = 0; c < 64; c += 4) {
                float4 a4 = *(const float4*)(arow + c);
                float4 s4 = *(const float4*)(srow + c);
                float e0 = __expf(s4.x * SCALE * a4.x);
                float e1 = __expf(s4.y * SCALE * a4.y);
                float e2 = __expf(s4.z * SCALE * a4.z);
                float e3 = __expf(s4.w * SCALE * a4.w);
                lsum += (e0 + e1) + (e2 + e3);
                __half2 h01 = __floats2half2_rn(e0, e1);
                __half2 h23 = __floats2half2_rn(e2, e3);
                pst[c/2]     = *(uint32_t*)&h01;
                pst[c/2 + 1] = *(uint32_t*)&h23;
            }
            lacc += lsum;
            __syncthreads();                // all S reads complete
            uint4* prow = (uint4*)(sP + row*LDH + half*64);
            #pragma unroll
            for (int g = 0; g < 8; g++)
                prow[g] = make_uint4(pst[g*4], pst[g*4+1], pst[g*4+2], pst[g*4+3]);
        }

        if (it < 15) { CP_WAIT1(); } else { CP_WAIT0(); }
        __syncthreads();                    // sV[it] + sP visible

        // ---- O += P @ V ----
        #pragma unroll
        for (int k = 0; k < 8; k++) {
            wmma::fragment<wmma::matrix_a,16,16,16,__half,wmma::row_major> aP;
            wmma::load_matrix_sync(aP, sP + (warp*16)*LDH + k*16, LDH);
            #pragma unroll
            for (int j = 0; j < 8; j++) {
                wmma::fragment<wmma::matrix_b,16,16,16,__half,wmma::row_major> bV;
                wmma::load_matrix_sync(bV, sV + (k*16)*LDH + j*16, LDH);
                wmma::mma_sync(oacc[j], aP, bV, oacc[j]);
            }
        }
        __syncthreads();                    // sV/sP free

        // ---- prefetch V[it+1] (hidden behind next S-GEMM + exp) ----
        if (it < 15) {
            const __half* vn = vp + (size_t)(m0 + 128)*DIM;
            for (int idx = tid; idx < 128*16; idx += 256) {
                int r = idx >> 4, c = idx & 15;
                cp16(uV + r*272 + c*16, vn + (size_t)r*DIM + c*8);
            }
            CP_COMMIT();
        }
    }

    // ---- epilogue: O / l -> g_ocat (fp16) ----
    sL[row][half] = lacc;
    #pragma unroll
    for (int j = 0; j < 8; j++)
        wmma::store_matrix_sync(sS + (warp*16)*LDS4 + j*16, oacc[j],
                                LDS4, wmma::mem_row_major);
    __syncthreads();
    {
        const float linv = 1.0f / (sL[row][0] + sL[row][1]);
        const float* orow = sS + row*LDS4 + half*64;
        __half2* drow = (__half2*)(g_ocat + (size_t)(b*NTOK + n0 + row)*FEAT
                                   + h*DIM + half*64);
        #pragma unroll
        for (int c = 0; c < 32; c++)
            drow[c] = __floats2half2_rn(orow[2*c] * linv, orow[2*c+1] * linv);
    }
}

// ============================================================
// K4a: outproj split-K partial (R4 proven): psum[z] = ocat[:,z*256:+256] @ Wout
// grid (64, 4, 4), block 128 (4 warps 2x2, each 32x32)
// ============================================================
__global__ void outproj_part(const float* __restrict__ Wout) {
    __shared__ __align__(16) char smem_raw[18432];
    __half* sA = (__half*)smem_raw;                 // 64 x 72
    __half* sB = (__half*)(smem_raw + 64*72*2);     // 64 x 72
    float*  sO = (float*)smem_raw;                  // 64 x 68 (alias after MMA)
    const int tid  = threadIdx.x;
    const int warp = tid >> 5;
    const int wr = warp >> 1, wc = warp & 1;
    const int r0 = blockIdx.x * 64, c0 = blockIdx.y * 64;
    const int k0 = blockIdx.z * 256;
    float* psum = g_psum[blockIdx.z];

    wmma::fragment<wmma::accumulator,16,16,16,float> acc[2][2];
    #pragma unroll
    for (int i = 0; i < 2; i++)
        #pragma unroll
        for (int j = 0; j < 2; j++) wmma::fill_fragment(acc[i][j], 0.0f);

    for (int kb = 0; kb < 256; kb += 64) {
        for (int idx = tid; idx < 64*8; idx += 128) {
            int r = idx >> 3, c = idx & 7;
            *(uint4*)(sA + r*72 + c*8) =
                *(const uint4*)(g_ocat + (size_t)(r0 + r)*FEAT + k0 + kb + c*8);
        }
        for (int idx = tid; idx < 64*16; idx += 128) {
            int r = idx >> 4, c = idx & 15;
            float4 t = *(const float4*)(Wout + (size_t)(k0 + kb + r)*DOUT + c0 + c*4);
            __half2* d = (__half2*)(sB + r*72 + c*4);
            d[0] = __floats2half2_rn(t.x, t.y);
            d[1] = __floats2half2_rn(t.z, t.w);
        }
        __syncthreads();
        #pragma unroll
        for (int kk = 0; kk < 4; kk++) {
            wmma::fragment<wmma::matrix_a,16,16,16,__half,wmma::row_major> fa[2];
            wmma::fragment<wmma::matrix_b,16,16,16,__half,wmma::row_major> fb[2];
            #pragma unroll
            for (int i = 0; i < 2; i++)
                wmma::load_matrix_sync(fa[i], sA + (wr*32 + i*16)*72 + kk*16, 72);
            #pragma unroll
            for (int j = 0; j < 2; j++)
                wmma::load_matrix_sync(fb[j], sB + (kk*16)*72 + wc*32 + j*16, 72);
            #pragma unroll
            for (int i = 0; i < 2; i++)
                #pragma unroll
                for (int j = 0; j < 2; j++)
                    wmma::mma_sync(acc[i][j], fa[i], fb[j], acc[i][j]);
        }
        __syncthreads();
    }
    #pragma unroll
    for (int i = 0; i < 2; i++)
        #pragma unroll
        for (int j = 0; j < 2; j++)
            wmma::store_matrix_sync(sO + (wr*32 + i*16)*68 + wc*32 + j*16,
                                    acc[i][j], 68, wmma::mem_row_major);
    __syncthreads();
    for (int idx = tid; idx < 64*64; idx += 128) {
        int r = idx >> 6, c = idx & 63;
        psum[(size_t)(r0 + r)*DOUT + c0 + c] = sO[r*68 + c];
    }
}

// ============================================================
// K4b: out = sum_z psum[z] + bout
// ============================================================
__global__ void outproj_reduce(const float* __restrict__ bout,
                               float* __restrict__ out) {
    size_t i = (size_t)blockIdx.x * blockDim.x + threadIdx.x;
    if (i < (size_t)BN_*DOUT) {
        float s = g_psum[0][i] + g_psum[1][i] + g_psum[2][i] + g_psum[3][i];
        out[i] = s + bout[i & (DOUT - 1)];
    }
}

// ============================================================
extern "C" void kernel_launch(void* const* d_in, const int* in_sizes, int n_in,
                              void* d_out, int out_size) {
    const float* X    = (const float*)d_in[0];
    const float* adj  = (const float*)d_in[1];
    const float* Wq   = (const float*)d_in[2];
    const float* bq   = (const float*)d_in[3];
    const float* Wk   = (const float*)d_in[4];
    const float* bk   = (const float*)d_in[5];
    const float* Wv   = (const float*)d_in[6];
    const float* bv   = (const float*)d_in[7];
    const float* Wout = (const float*)d_in[8];
    const float* bout = (const float*)d_in[9];
    float* out = (float*)d_out;

    const int fused_smem = 3*34816 + 67584;   // 172,032 B
    cudaFuncSetAttribute(fused_attn_fp16,
                         cudaFuncAttributeMaxDynamicSharedMemorySize, fused_smem);

    {
        size_t total = (size_t)BB*NTOK*NTOK;
        adjsum_kernel<<<(unsigned)((total + 255) / 256), 256>>>((const float4*)adj);
    }
    qkv_kernel<<<dim3(BN_/64, 3*NH), 256>>>(X, Wq, bq, Wk, bk, Wv, bv);
    fused_attn_fp16<<<dim3(NTOK/128, BB*NH), 256, fused_smem>>>();
    outproj_part<<<dim3(BN_/64, DOUT/64, 4), 128>>>(Wout);
    {
        size_t total = (size_t)BN_*DOUT;
        outproj_reduce<<<(unsigned)((total + 255) / 256), 256>>>(bout, out);
    }
}

// round 8
// speedup vs baseline: 1.8375x; 1.4902x over previous
#include <cuda_runtime.h>
#include <cuda_fp16.h>
#include <mma.h>
#include <cstdint>

using namespace nvcuda;

#define BB    2
#define NTOK  2048
#define DIM   128
#define NH    8
#define DOUT  256
#define BN_   (BB*NTOK)            // 4096
#define FEAT  (NH*DIM)             // 1024
#define SCALE 0.022097086912079608f  // 1/sqrt(2048)
#define LDH   136                  // fp16 tile leading dim (272 B rows)
#define LDS4  132                  // fp32 staging leading dim (qkv kernel)
#define TB    34816                // one 128 x LDH fp16 tile buffer

// ---- scratch (sanctioned __device__ globals) ----
__device__ __align__(16) __half g_adjsumh[(size_t)BB*NTOK*NTOK];    // 16.8 MB
__device__ __align__(16) __half g_q[(size_t)NH*BN_*DIM];            // 8.4 MB
__device__ __align__(16) __half g_k[(size_t)NH*BN_*DIM];
__device__ __align__(16) __half g_v[(size_t)NH*BN_*DIM];
__device__ __align__(16) __half g_ocat[(size_t)BN_*FEAT];           // 8.4 MB
__device__ float g_psum[4][(size_t)BN_*DOUT];                       // 16.8 MB

// ---- PTX helpers ----
__device__ __forceinline__ void cp16(uint32_t saddr, const void* gptr) {
    asm volatile("cp.async.cg.shared.global [%0], [%1], 16;"
                 :: "r"(saddr), "l"(gptr));
}
#define CP_COMMIT() asm volatile("cp.async.commit_group;" ::: "memory")
#define CP_WAIT1()  asm volatile("cp.async.wait_group 1;" ::: "memory")
#define CP_WAIT0()  asm volatile("cp.async.wait_group 0;" ::: "memory")

__device__ __forceinline__ void ldsm_x4(uint32_t& r0, uint32_t& r1,
                                        uint32_t& r2, uint32_t& r3, uint32_t a) {
    asm volatile("ldmatrix.sync.aligned.m8n8.x4.shared.b16 {%0,%1,%2,%3}, [%4];"
                 : "=r"(r0), "=r"(r1), "=r"(r2), "=r"(r3) : "r"(a));
}
__device__ __forceinline__ void ldsm_x4t(uint32_t& r0, uint32_t& r1,
                                         uint32_t& r2, uint32_t& r3, uint32_t a) {
    asm volatile("ldmatrix.sync.aligned.m8n8.x4.trans.shared.b16 {%0,%1,%2,%3}, [%4];"
                 : "=r"(r0), "=r"(r1), "=r"(r2), "=r"(r3) : "r"(a));
}
__device__ __forceinline__ void mma16816(float* c, const uint32_t* a,
                                         uint32_t b0, uint32_t b1) {
    asm volatile("mma.sync.aligned.m16n8k16.row.col.f32.f16.f16.f32 "
                 "{%0,%1,%2,%3}, {%4,%5,%6,%7}, {%8,%9}, {%0,%1,%2,%3};"
                 : "+f"(c[0]), "+f"(c[1]), "+f"(c[2]), "+f"(c[3])
                 : "r"(a[0]), "r"(a[1]), "r"(a[2]), "r"(a[3]), "r"(b0), "r"(b1));
}

// ============================================================
// K1: adjsumh[b,n,m] = fp16( sum_w nodeadj[b,n,m,w] )
// ============================================================
__global__ void adjsum_kernel(const float4* __restrict__ adj) {
    size_t i = (size_t)blockIdx.x * blockDim.x + threadIdx.x;
    if (i < (size_t)BB*NTOK*NTOK) {
        float4 t = adj[i];
        g_adjsumh[i] = __float2half_rn((t.x + t.y) + (t.z + t.w));
    }
}

// ============================================================
// K2: q/k/v[h] = fp16( X @ W[h] + b[h] )   (unchanged, proven)
// ============================================================
__global__ void qkv_kernel(const float* __restrict__ X,
                           const float* __restrict__ Wq, const float* __restrict__ bq,
                           const float* __restrict__ Wk, const float* __restrict__ bk,
                           const float* __restrict__ Wv, const float* __restrict__ bv) {
    __shared__ __align__(16) char smem_raw[17408 + TB];
    __half* sA = (__half*)smem_raw;
    __half* sB = (__half*)(smem_raw + 17408);
    float*  sO = (float*)(smem_raw + 17408);
    const int tid  = threadIdx.x;
    const int warp = tid >> 5;
    const int wr = warp >> 2, wc = warp & 3;
    const int row0 = blockIdx.x * 64;
    const int z = blockIdx.y;
    const int mat = z >> 3, h = z & 7;

    const float* Wm = (mat == 0 ? Wq : (mat == 1 ? Wk : Wv)) + (size_t)h*DIM*DIM;
    const float* bm = (mat == 0 ? bq : (mat == 1 ? bk : bv)) + (size_t)h*DIM;
    __half* outp = (mat == 0 ? g_q : (mat == 1 ? g_k : g_v)) + (size_t)h*BN_*DIM;

    for (int idx = tid; idx < 64*32; idx += 256) {
        int r = idx >> 5, c = idx & 31;
        float4 t = *(const float4*)(X + (size_t)(row0 + r)*DIM + c*4);
        __half2* d = (__half2*)(sA + r*LDH + c*4);
        d[0] = __floats2half2_rn(t.x, t.y);
        d[1] = __floats2half2_rn(t.z, t.w);
    }
    for (int idx = tid; idx < 128*32; idx += 256) {
        int r = idx >> 5, c = idx & 31;
        float4 t = *(const float4*)(Wm + (size_t)r*DIM + c*4);
        __half2* d = (__half2*)(sB + r*LDH + c*4);
        d[0] = __floats2half2_rn(t.x, t.y);
        d[1] = __floats2half2_rn(t.z, t.w);
    }
    __syncthreads();

    wmma::fragment<wmma::accumulator,16,16,16,float> acc[2][2];
    #pragma unroll
    for (int i = 0; i < 2; i++)
        #pragma unroll
        for (int j = 0; j < 2; j++) wmma::fill_fragment(acc[i][j], 0.0f);

    #pragma unroll
    for (int k = 0; k < 8; k++) {
        wmma::fragment<wmma::matrix_a,16,16,16,__half,wmma::row_major> fa[2];
        wmma::fragment<wmma::matrix_b,16,16,16,__half,wmma::row_major> fb[2];
        #pragma unroll
        for (int i = 0; i < 2; i++)
            wmma::load_matrix_sync(fa[i], sA + (wr*32 + i*16)*LDH + k*16, LDH);
        #pragma unroll
        for (int j = 0; j < 2; j++)
            wmma::load_matrix_sync(fb[j], sB + (k*16)*LDH + wc*32 + j*16, LDH);
        #pragma unroll
        for (int i = 0; i < 2; i++)
            #pragma unroll
            for (int j = 0; j < 2; j++)
                wmma::mma_sync(acc[i][j], fa[i], fb[j], acc[i][j]);
    }
    __syncthreads();
    #pragma unroll
    for (int i = 0; i < 2; i++)
        #pragma unroll
        for (int j = 0; j < 2; j++)
            wmma::store_matrix_sync(sO + (wr*32 + i*16)*LDS4 + wc*32 + j*16,
                                    acc[i][j], LDS4, wmma::mem_row_major);
    __syncthreads();
    for (int idx = tid; idx < 64*128; idx += 256) {
        int r = idx >> 7, e = idx & 127;
        outp[(size_t)(row0 + r)*DIM + e] = __float2half_rn(sO[r*LDS4 + e] + bm[e]);
    }
}

// ============================================================
// K3 (FUSED, FA2-style register softmax, raw mma.m16n8k16):
// grid (16,16), 256 threads (8 warps; warp w owns Q rows w*16..+15).
// smem (dynamic, 208,896 B): K0 K1 V0 V1 A0 A1 (each 128 x 136 fp16),
// double-buffered via cp.async; Q staged through sK0 then register-resident.
// ============================================================
__global__ __launch_bounds__(256, 1) void fused_attn_fa2() {
    extern __shared__ __align__(16) char dsm[];
    const uint32_t uBase = (uint32_t)__cvta_generic_to_shared(dsm);

    const int tid  = threadIdx.x;
    const int warp = tid >> 5;
    const int lane = tid & 31;
    const int g    = lane >> 2;          // 0..7
    const int tg   = lane & 3;           // 0..3
    const int n0 = blockIdx.x * 128;
    const int b = blockIdx.y >> 3, h = blockIdx.y & 7;

    const __half* qp  = g_q + (size_t)h*BN_*DIM + (size_t)b*NTOK*DIM;
    const __half* kp  = g_k + (size_t)h*BN_*DIM + (size_t)b*NTOK*DIM;
    const __half* vp  = g_v + (size_t)h*BN_*DIM + (size_t)b*NTOK*DIM;
    const __half* adjp = g_adjsumh + (size_t)b*NTOK*NTOK + (size_t)n0*NTOK;

    // ldmatrix lane-address components
    const int lrow_a = ((lane >> 3) & 1)*8 + (lane & 7);  // Q/V row-in-16
    const int lcol_a = (lane >> 4)*8;                     // Q/V col-in-16
    const int lrow_b = ((lane >> 4) & 1)*8 + (lane & 7);  // K row-in-16
    const int lcol_b = ((lane >> 3) & 1)*8;               // K col-in-16

    // ---- prologue: stage Q through sK0, extract a-frags ----
    for (int idx = tid; idx < 128*16; idx += 256) {
        int r = idx >> 4, c = idx & 15;
        *(uint4*)(dsm + r*272 + c*16) = *(const uint4*)(qp + (size_t)(n0 + r)*DIM + c*8);
    }
    __syncthreads();
    uint32_t aQ[8][4];
    #pragma unroll
    for (int kk = 0; kk < 8; kk++) {
        uint32_t a = uBase + (uint32_t)(warp*16 + lrow_a)*272 + (kk*16 + lcol_a)*2;
        ldsm_x4(aQ[kk][0], aQ[kk][1], aQ[kk][2], aQ[kk][3], a);
    }
    __syncthreads();

    // ---- issue G0, G1 ({K,V,adj} per kv-tile) ----
    #pragma unroll
    for (int j = 0; j < 2; j++) {
        const uint32_t uK = uBase + j*TB, uV = uBase + (2 + j)*TB, uA = uBase + (4 + j)*TB;
        const int m0 = j*128;
        for (int idx = tid; idx < 128*16; idx += 256) {
            int r = idx >> 4, c = idx & 15;
            cp16(uK + r*272 + c*16, kp + (size_t)(m0 + r)*DIM + c*8);
        }
        for (int idx = tid; idx < 128*16; idx += 256) {
            int r = idx >> 4, c = idx & 15;
            cp16(uV + r*272 + c*16, vp + (size_t)(m0 + r)*DIM + c*8);
        }
        for (int idx = tid; idx < 128*16; idx += 256) {
            int r = idx >> 4, c = idx & 15;
            cp16(uA + r*272 + c*16, adjp + (size_t)r*NTOK + m0 + c*8);
        }
        CP_COMMIT();
    }

    float oacc[16][4];
    #pragma unroll
    for (int j = 0; j < 16; j++)
        #pragma unroll
        for (int e = 0; e < 4; e++) oacc[j][e] = 0.f;
    float lsum0 = 0.f, lsum1 = 0.f;

    for (int it = 0; it < 16; it++) {
        const int bi = it & 1;
        const uint32_t uK = uBase + bi*TB;
        const uint32_t uV = uBase + (2 + bi)*TB;
        const __half* sAdj = (const __half*)(dsm + (size_t)(4 + bi)*TB);

        if (it < 15) { CP_WAIT1(); } else { CP_WAIT0(); }
        __syncthreads();

        // ---- S = Q K^T (sacc[16 j-tiles][4]) ----
        float sacc[16][4];
        #pragma unroll
        for (int j = 0; j < 16; j++)
            #pragma unroll
            for (int e = 0; e < 4; e++) sacc[j][e] = 0.f;
        #pragma unroll
        for (int kk = 0; kk < 8; kk++) {
            #pragma unroll
            for (int jjp = 0; jjp < 8; jjp++) {
                uint32_t r0, r1, r2, r3;
                ldsm_x4(r0, r1, r2, r3,
                        uK + (uint32_t)(jjp*16 + lrow_b)*272 + (kk*16 + lcol_b)*2);
                mma16816(sacc[2*jjp],     aQ[kk], r0, r1);
                mma16816(sacc[2*jjp + 1], aQ[kk], r2, r3);
            }
        }

        // ---- exp in registers: P a-frags + row sums ----
        uint32_t aP[8][4];
        const int row0 = warp*16 + g;
        #pragma unroll
        for (int jj = 0; jj < 16; jj++) {
            const int col = jj*8 + tg*2;
            float2 a0 = __half22float2(*(const __half2*)(sAdj + row0*LDH + col));
            float2 a1 = __half22float2(*(const __half2*)(sAdj + (row0 + 8)*LDH + col));
            float e00 = __expf(sacc[jj][0] * SCALE * a0.x);
            float e01 = __expf(sacc[jj][1] * SCALE * a0.y);
            float e10 = __expf(sacc[jj][2] * SCALE * a1.x);
            float e11 = __expf(sacc[jj][3] * SCALE * a1.y);
            lsum0 += e00 + e01;
            lsum1 += e10 + e11;
            __half2 p0 = __floats2half2_rn(e00, e01);
            __half2 p1 = __floats2half2_rn(e10, e11);
            aP[jj >> 1][(jj & 1)*2 + 0] = *(uint32_t*)&p0;
            aP[jj >> 1][(jj & 1)*2 + 1] = *(uint32_t*)&p1;
        }

        // ---- O += P @ V ----
        #pragma unroll
        for (int kk = 0; kk < 8; kk++) {
            #pragma unroll
            for (int jop = 0; jop < 8; jop++) {
                uint32_t r0, r1, r2, r3;
                ldsm_x4t(r0, r1, r2, r3,
                         uV + (uint32_t)(kk*16 + lrow_a)*272 + (jop*16 + lcol_a)*2);
                mma16816(oacc[2*jop],     aP[kk], r0, r1);
                mma16816(oacc[2*jop + 1], aP[kk], r2, r3);
            }
        }
        __syncthreads();   // all warps done with buffers bi (K,V,adj)

        // ---- issue G(it+2) into buffers bi ----
        if (it + 2 < 16) {
            const int m2 = (it + 2)*128;
            for (int idx = tid; idx < 128*16; idx += 256) {
                int r = idx >> 4, c = idx & 15;
                cp16(uK + r*272 + c*16, kp + (size_t)(m2 + r)*DIM + c*8);
            }
            for (int idx = tid; idx < 128*16; idx += 256) {
                int r = idx >> 4, c = idx & 15;
                cp16(uV + r*272 + c*16, vp + (size_t)(m2 + r)*DIM + c*8);
            }
            const uint32_t uA = uBase + (4 + bi)*TB;
            for (int idx = tid; idx < 128*16; idx += 256) {
                int r = idx >> 4, c = idx & 15;
                cp16(uA + r*272 + c*16, adjp + (size_t)r*NTOK + m2 + c*8);
            }
            CP_COMMIT();
        }
    }

    // ---- epilogue: quad-reduce row sums, normalize, write g_ocat ----
    lsum0 += __shfl_xor_sync(0xFFFFFFFF, lsum0, 1);
    lsum0 += __shfl_xor_sync(0xFFFFFFFF, lsum0, 2);
    lsum1 += __shfl_xor_sync(0xFFFFFFFF, lsum1, 1);
    lsum1 += __shfl_xor_sync(0xFFFFFFFF, lsum1, 2);
    const float inv0 = 1.0f / lsum0;
    const float inv1 = 1.0f / lsum1;
    const int row0 = warp*16 + g;
    __half* ob0 = g_ocat + (size_t)(b*NTOK + n0 + row0)*FEAT + h*DIM;
    __half* ob1 = g_ocat + (size_t)(b*NTOK + n0 + row0 + 8)*FEAT + h*DIM;
    #pragma unroll
    for (int jo = 0; jo < 16; jo++) {
        const int col = jo*8 + tg*2;
        *(__half2*)(ob0 + col) = __floats2half2_rn(oacc[jo][0]*inv0, oacc[jo][1]*inv0);
        *(__half2*)(ob1 + col) = __floats2half2_rn(oacc[jo][2]*inv1, oacc[jo][3]*inv1);
    }
}

// ============================================================
// K4a: outproj split-K partial (proven): psum[z] = ocat[:,z*256:+256] @ Wout
// grid (64, 4, 4), block 128
// ============================================================
__global__ void outproj_part(const float* __restrict__ Wout) {
    __shared__ __align__(16) char smem_raw[18432];
    __half* sA = (__half*)smem_raw;
    __half* sB = (__half*)(smem_raw + 64*72*2);
    float*  sO = (float*)smem_raw;
    const int tid  = threadIdx.x;
    const int warp = tid >> 5;
    const int wr = warp >> 1, wc = warp & 1;
    const int r0 = blockIdx.x * 64, c0 = blockIdx.y * 64;
    const int k0 = blockIdx.z * 256;
    float* psum = g_psum[blockIdx.z];

    wmma::fragment<wmma::accumulator,16,16,16,float> acc[2][2];
    #pragma unroll
    for (int i = 0; i < 2; i++)
        #pragma unroll
        for (int j = 0; j < 2; j++) wmma::fill_fragment(acc[i][j], 0.0f);

    for (int kb = 0; kb < 256; kb += 64) {
        for (int idx = tid; idx < 64*8; idx += 128) {
            int r = idx >> 3, c = idx & 7;
            *(uint4*)(sA + r*72 + c*8) =
                *(const uint4*)(g_ocat + (size_t)(r0 + r)*FEAT + k0 + kb + c*8);
        }
        for (int idx = tid; idx < 64*16; idx += 128) {
            int r = idx >> 4, c = idx & 15;
            float4 t = *(const float4*)(Wout + (size_t)(k0 + kb + r)*DOUT + c0 + c*4);
            __half2* d = (__half2*)(sB + r*72 + c*4);
            d[0] = __floats2half2_rn(t.x, t.y);
            d[1] = __floats2half2_rn(t.z, t.w);
        }
        __syncthreads();
        #pragma unroll
        for (int kk = 0; kk < 4; kk++) {
            wmma::fragment<wmma::matrix_a,16,16,16,__half,wmma::row_major> fa[2];
            wmma::fragment<wmma::matrix_b,16,16,16,__half,wmma::row_major> fb[2];
            #pragma unroll
            for (int i = 0; i < 2; i++)
                wmma::load_matrix_sync(fa[i], sA + (wr*32 + i*16)*72 + kk*16, 72);
            #pragma unroll
            for (int j = 0; j < 2; j++)
                wmma::load_matrix_sync(fb[j], sB + (kk*16)*72 + wc*32 + j*16, 72);
            #pragma unroll
            for (int i = 0; i < 2; i++)
                #pragma unroll
                for (int j = 0; j < 2; j++)
                    wmma::mma_sync(acc[i][j], fa[i], fb[j], acc[i][j]);
        }
        __syncthreads();
    }
    #pragma unroll
    for (int i = 0; i < 2; i++)
        #pragma unroll
        for (int j = 0; j < 2; j++)
            wmma::store_matrix_sync(sO + (wr*32 + i*16)*68 + wc*32 + j*16,
                                    acc[i][j], 68, wmma::mem_row_major);
    __syncthreads();
    for (int idx = tid; idx < 64*64; idx += 128) {
        int r = idx >> 6, c = idx & 63;
        psum[(size_t)(r0 + r)*DOUT + c0 + c] = sO[r*68 + c];
    }
}

// ============================================================
// K4b: out = sum_z psum[z] + bout
// ============================================================
__global__ void outproj_reduce(const float* __restrict__ bout,
                               float* __restrict__ out) {
    size_t i = (size_t)blockIdx.x * blockDim.x + threadIdx.x;
    if (i < (size_t)BN_*DOUT) {
        float s = g_psum[0][i] + g_psum[1][i] + g_psum[2][i] + g_psum[3][i];
        out[i] = s + bout[i & (DOUT - 1)];
    }
}

// ============================================================
extern "C" void kernel_launch(void* const* d_in, const int* in_sizes, int n_in,
                              void* d_out, int out_size) {
    const float* X    = (const float*)d_in[0];
    const float* adj  = (const float*)d_in[1];
    const float* Wq   = (const float*)d_in[2];
    const float* bq   = (const float*)d_in[3];
    const float* Wk   = (const float*)d_in[4];
    const float* bk   = (const float*)d_in[5];
    const float* Wv   = (const float*)d_in[6];
    const float* bv   = (const float*)d_in[7];
    const float* Wout = (const float*)d_in[8];
    const float* bout = (const float*)d_in[9];
    float* out = (float*)d_out;

    const int fused_smem = 6*TB;   // 208,896 B
    cudaFuncSetAttribute(fused_attn_fa2,
                         cudaFuncAttributeMaxDynamicSharedMemorySize, fused_smem);

    {
        size_t total = (size_t)BB*NTOK*NTOK;
        adjsum_kernel<<<(unsigned)((total + 255) / 256), 256>>>((const float4*)adj);
    }
    qkv_kernel<<<dim3(BN_/64, 3*NH), 256>>>(X, Wq, bq, Wk, bk, Wv, bv);
    fused_attn_fa2<<<dim3(NTOK/128, BB*NH), 256, fused_smem>>>();
    outproj_part<<<dim3(BN_/64, DOUT/64, 4), 128>>>(Wout);
    {
        size_t total = (size_t)BN_*DOUT;
        outproj_reduce<<<(unsigned)((total + 255) / 256), 256>>>(bout, out);
    }
}

// round 9
// speedup vs baseline: 1.9090x; 1.0389x over previous
#include <cuda_runtime.h>
#include <cuda_fp16.h>
#include <mma.h>
#include <cstdint>

using namespace nvcuda;

#define BB    2
#define NTOK  2048
#define DIM   128
#define NH    8
#define DOUT  256
#define BN_   (BB*NTOK)            // 4096
#define FEAT  (NH*DIM)             // 1024
#define SC2E  0.03187935797f       // (1/sqrt(2048)) * log2(e)
#define LDH   136                  // fp16 tile leading dim (272 B rows)
#define LDS4  132                  // fp32 staging leading dim (qkv kernel)
#define TB    34816                // one 128 x LDH fp16 tile buffer

#define ADJ_GRID  32768            // 8.39M float4 / 256
#define BIAS_GRID 1024             // 262144 float4 / 256

// ---- scratch (sanctioned __device__ globals) ----
__device__ __align__(16) __half g_adjsumh[(size_t)BB*NTOK*NTOK];    // 16.8 MB
__device__ __align__(16) __half g_q[(size_t)NH*BN_*DIM];            // 8.4 MB
__device__ __align__(16) __half g_k[(size_t)NH*BN_*DIM];
__device__ __align__(16) __half g_v[(size_t)NH*BN_*DIM];
__device__ __align__(16) __half g_ocat[(size_t)BN_*FEAT];           // 8.4 MB

// ---- PTX helpers ----
__device__ __forceinline__ void cp16(uint32_t saddr, const void* gptr) {
    asm volatile("cp.async.cg.shared.global [%0], [%1], 16;"
                 :: "r"(saddr), "l"(gptr));
}
#define CP_COMMIT() asm volatile("cp.async.commit_group;" ::: "memory")
#define CP_WAIT1()  asm volatile("cp.async.wait_group 1;" ::: "memory")
#define CP_WAIT0()  asm volatile("cp.async.wait_group 0;" ::: "memory")

__device__ __forceinline__ void ldsm_x4(uint32_t& r0, uint32_t& r1,
                                        uint32_t& r2, uint32_t& r3, uint32_t a) {
    asm volatile("ldmatrix.sync.aligned.m8n8.x4.shared.b16 {%0,%1,%2,%3}, [%4];"
                 : "=r"(r0), "=r"(r1), "=r"(r2), "=r"(r3) : "r"(a));
}
__device__ __forceinline__ void ldsm_x4t(uint32_t& r0, uint32_t& r1,
                                         uint32_t& r2, uint32_t& r3, uint32_t a) {
    asm volatile("ldmatrix.sync.aligned.m8n8.x4.trans.shared.b16 {%0,%1,%2,%3}, [%4];"
                 : "=r"(r0), "=r"(r1), "=r"(r2), "=r"(r3) : "r"(a));
}
__device__ __forceinline__ void mma16816(float* c, const uint32_t* a,
                                         uint32_t b0, uint32_t b1) {
    asm volatile("mma.sync.aligned.m16n8k16.row.col.f32.f16.f16.f32 "
                 "{%0,%1,%2,%3}, {%4,%5,%6,%7}, {%8,%9}, {%0,%1,%2,%3};"
                 : "+f"(c[0]), "+f"(c[1]), "+f"(c[2]), "+f"(c[3])
                 : "r"(a[0]), "r"(a[1]), "r"(a[2]), "r"(a[3]), "r"(b0), "r"(b1));
}
__device__ __forceinline__ float ex2f(float x) {
    float y;
    asm("ex2.approx.ftz.f32 %0, %1;" : "=f"(y) : "f"(x));
    return y;
}

// ============================================================
// K1: blocks [0, ADJ_GRID): adjsumh = fp16(sum_w adj);
//     blocks [ADJ_GRID, +BIAS_GRID): out = bias broadcast (pre-init for atomics)
// ============================================================
__global__ void adjsum_kernel(const float4* __restrict__ adj,
                              const float4* __restrict__ bout4,
                              float4* __restrict__ out4) {
    const int tid = threadIdx.x;
    if (blockIdx.x < ADJ_GRID) {
        size_t i = (size_t)blockIdx.x * 256 + tid;
        float4 t = adj[i];
        g_adjsumh[i] = __float2half_rn((t.x + t.y) + (t.z + t.w));
    } else {
        size_t j = (size_t)(blockIdx.x - ADJ_GRID) * 256 + tid;
        out4[j] = bout4[j & 63];
    }
}

// ============================================================
// K2: q/k/v[h] = fp16( X @ W[h] + b[h] )   (unchanged, proven)
// ============================================================
__global__ void qkv_kernel(const float* __restrict__ X,
                           const float* __restrict__ Wq, const float* __restrict__ bq,
                           const float* __restrict__ Wk, const float* __restrict__ bk,
                           const float* __restrict__ Wv, const float* __restrict__ bv) {
    __shared__ __align__(16) char smem_raw[17408 + TB];
    __half* sA = (__half*)smem_raw;
    __half* sB = (__half*)(smem_raw + 17408);
    float*  sO = (float*)(smem_raw + 17408);
    const int tid  = threadIdx.x;
    const int warp = tid >> 5;
    const int wr = warp >> 2, wc = warp & 3;
    const int row0 = blockIdx.x * 64;
    const int z = blockIdx.y;
    const int mat = z >> 3, h = z & 7;

    const float* Wm = (mat == 0 ? Wq : (mat == 1 ? Wk : Wv)) + (size_t)h*DIM*DIM;
    const float* bm = (mat == 0 ? bq : (mat == 1 ? bk : bv)) + (size_t)h*DIM;
    __half* outp = (mat == 0 ? g_q : (mat == 1 ? g_k : g_v)) + (size_t)h*BN_*DIM;

    for (int idx = tid; idx < 64*32; idx += 256) {
        int r = idx >> 5, c = idx & 31;
        float4 t = *(const float4*)(X + (size_t)(row0 + r)*DIM + c*4);
        __half2* d = (__half2*)(sA + r*LDH + c*4);
        d[0] = __floats2half2_rn(t.x, t.y);
        d[1] = __floats2half2_rn(t.z, t.w);
    }
    for (int idx = tid; idx < 128*32; idx += 256) {
        int r = idx >> 5, c = idx & 31;
        float4 t = *(const float4*)(Wm + (size_t)r*DIM + c*4);
        __half2* d = (__half2*)(sB + r*LDH + c*4);
        d[0] = __floats2half2_rn(t.x, t.y);
        d[1] = __floats2half2_rn(t.z, t.w);
    }
    __syncthreads();

    wmma::fragment<wmma::accumulator,16,16,16,float> acc[2][2];
    #pragma unroll
    for (int i = 0; i < 2; i++)
        #pragma unroll
        for (int j = 0; j < 2; j++) wmma::fill_fragment(acc[i][j], 0.0f);

    #pragma unroll
    for (int k = 0; k < 8; k++) {
        wmma::fragment<wmma::matrix_a,16,16,16,__half,wmma::row_major> fa[2];
        wmma::fragment<wmma::matrix_b,16,16,16,__half,wmma::row_major> fb[2];
        #pragma unroll
        for (int i = 0; i < 2; i++)
            wmma::load_matrix_sync(fa[i], sA + (wr*32 + i*16)*LDH + k*16, LDH);
        #pragma unroll
        for (int j = 0; j < 2; j++)
            wmma::load_matrix_sync(fb[j], sB + (k*16)*LDH + wc*32 + j*16, LDH);
        #pragma unroll
        for (int i = 0; i < 2; i++)
            #pragma unroll
            for (int j = 0; j < 2; j++)
                wmma::mma_sync(acc[i][j], fa[i], fb[j], acc[i][j]);
    }
    __syncthreads();
    #pragma unroll
    for (int i = 0; i < 2; i++)
        #pragma unroll
        for (int j = 0; j < 2; j++)
            wmma::store_matrix_sync(sO + (wr*32 + i*16)*LDS4 + wc*32 + j*16,
                                    acc[i][j], LDS4, wmma::mem_row_major);
    __syncthreads();
    for (int idx = tid; idx < 64*128; idx += 256) {
        int r = idx >> 7, e = idx & 127;
        outp[(size_t)(row0 + r)*DIM + e] = __float2half_rn(sO[r*LDS4 + e] + bm[e]);
    }
}

// ============================================================
// K3 (FUSED FA2, unchanged except ex2 fold)
// ============================================================
__global__ __launch_bounds__(256, 1) void fused_attn_fa2() {
    extern __shared__ __align__(16) char dsm[];
    const uint32_t uBase = (uint32_t)__cvta_generic_to_shared(dsm);

    const int tid  = threadIdx.x;
    const int warp = tid >> 5;
    const int lane = tid & 31;
    const int g    = lane >> 2;
    const int tg   = lane & 3;
    const int n0 = blockIdx.x * 128;
    const int b = blockIdx.y >> 3, h = blockIdx.y & 7;

    const __half* qp  = g_q + (size_t)h*BN_*DIM + (size_t)b*NTOK*DIM;
    const __half* kp  = g_k + (size_t)h*BN_*DIM + (size_t)b*NTOK*DIM;
    const __half* vp  = g_v + (size_t)h*BN_*DIM + (size_t)b*NTOK*DIM;
    const __half* adjp = g_adjsumh + (size_t)b*NTOK*NTOK + (size_t)n0*NTOK;

    const int lrow_a = ((lane >> 3) & 1)*8 + (lane & 7);
    const int lcol_a = (lane >> 4)*8;
    const int lrow_b = ((lane >> 4) & 1)*8 + (lane & 7);
    const int lcol_b = ((lane >> 3) & 1)*8;

    // ---- prologue: stage Q through sK0, extract a-frags ----
    for (int idx = tid; idx < 128*16; idx += 256) {
        int r = idx >> 4, c = idx & 15;
        *(uint4*)(dsm + r*272 + c*16) = *(const uint4*)(qp + (size_t)(n0 + r)*DIM + c*8);
    }
    __syncthreads();
    uint32_t aQ[8][4];
    #pragma unroll
    for (int kk = 0; kk < 8; kk++) {
        uint32_t a = uBase + (uint32_t)(warp*16 + lrow_a)*272 + (kk*16 + lcol_a)*2;
        ldsm_x4(aQ[kk][0], aQ[kk][1], aQ[kk][2], aQ[kk][3], a);
    }
    __syncthreads();

    #pragma unroll
    for (int j = 0; j < 2; j++) {
        const uint32_t uK = uBase + j*TB, uV = uBase + (2 + j)*TB, uA = uBase + (4 + j)*TB;
        const int m0 = j*128;
        for (int idx = tid; idx < 128*16; idx += 256) {
            int r = idx >> 4, c = idx & 15;
            cp16(uK + r*272 + c*16, kp + (size_t)(m0 + r)*DIM + c*8);
        }
        for (int idx = tid; idx < 128*16; idx += 256) {
            int r = idx >> 4, c = idx & 15;
            cp16(uV + r*272 + c*16, vp + (size_t)(m0 + r)*DIM + c*8);
        }
        for (int idx = tid; idx < 128*16; idx += 256) {
            int r = idx >> 4, c = idx & 15;
            cp16(uA + r*272 + c*16, adjp + (size_t)r*NTOK + m0 + c*8);
        }
        CP_COMMIT();
    }

    float oacc[16][4];
    #pragma unroll
    for (int j = 0; j < 16; j++)
        #pragma unroll
        for (int e = 0; e < 4; e++) oacc[j][e] = 0.f;
    float lsum0 = 0.f, lsum1 = 0.f;

    for (int it = 0; it < 16; it++) {
        const int bi = it & 1;
        const uint32_t uK = uBase + bi*TB;
        const uint32_t uV = uBase + (2 + bi)*TB;
        const __half* sAdj = (const __half*)(dsm + (size_t)(4 + bi)*TB);

        if (it < 15) { CP_WAIT1(); } else { CP_WAIT0(); }
        __syncthreads();

        // ---- S = Q K^T ----
        float sacc[16][4];
        #pragma unroll
        for (int j = 0; j < 16; j++)
            #pragma unroll
            for (int e = 0; e < 4; e++) sacc[j][e] = 0.f;
        #pragma unroll
        for (int kk = 0; kk < 8; kk++) {
            #pragma unroll
            for (int jjp = 0; jjp < 8; jjp++) {
                uint32_t r0, r1, r2, r3;
                ldsm_x4(r0, r1, r2, r3,
                        uK + (uint32_t)(jjp*16 + lrow_b)*272 + (kk*16 + lcol_b)*2);
                mma16816(sacc[2*jjp],     aQ[kk], r0, r1);
                mma16816(sacc[2*jjp + 1], aQ[kk], r2, r3);
            }
        }

        // ---- exp in registers (ex2 with folded scale) ----
        uint32_t aP[8][4];
        const int row0 = warp*16 + g;
        #pragma unroll
        for (int jj = 0; jj < 16; jj++) {
            const int col = jj*8 + tg*2;
            float2 a0 = __half22float2(*(const __half2*)(sAdj + row0*LDH + col));
            float2 a1 = __half22float2(*(const __half2*)(sAdj + (row0 + 8)*LDH + col));
            float e00 = ex2f(sacc[jj][0] * SC2E * a0.x);
            float e01 = ex2f(sacc[jj][1] * SC2E * a0.y);
            float e10 = ex2f(sacc[jj][2] * SC2E * a1.x);
            float e11 = ex2f(sacc[jj][3] * SC2E * a1.y);
            lsum0 += e00 + e01;
            lsum1 += e10 + e11;
            __half2 p0 = __floats2half2_rn(e00, e01);
            __half2 p1 = __floats2half2_rn(e10, e11);
            aP[jj >> 1][(jj & 1)*2 + 0] = *(uint32_t*)&p0;
            aP[jj >> 1][(jj & 1)*2 + 1] = *(uint32_t*)&p1;
        }

        // ---- O += P @ V ----
        #pragma unroll
        for (int kk = 0; kk < 8; kk++) {
            #pragma unroll
            for (int jop = 0; jop < 8; jop++) {
                uint32_t r0, r1, r2, r3;
                ldsm_x4t(r0, r1, r2, r3,
                         uV + (uint32_t)(kk*16 + lrow_a)*272 + (jop*16 + lcol_a)*2);
                mma16816(oacc[2*jop],     aP[kk], r0, r1);
                mma16816(oacc[2*jop + 1], aP[kk], r2, r3);
            }
        }
        __syncthreads();

        if (it + 2 < 16) {
            const int m2 = (it + 2)*128;
            for (int idx = tid; idx < 128*16; idx += 256) {
                int r = idx >> 4, c = idx & 15;
                cp16(uK + r*272 + c*16, kp + (size_t)(m2 + r)*DIM + c*8);
            }
            for (int idx = tid; idx < 128*16; idx += 256) {
                int r = idx >> 4, c = idx & 15;
                cp16(uV + r*272 + c*16, vp + (size_t)(m2 + r)*DIM + c*8);
            }
            const uint32_t uA = uBase + (4 + bi)*TB;
            for (int idx = tid; idx < 128*16; idx += 256) {
                int r = idx >> 4, c = idx & 15;
                cp16(uA + r*272 + c*16, adjp + (size_t)r*NTOK + m2 + c*8);
            }
            CP_COMMIT();
        }
    }

    // ---- epilogue ----
    lsum0 += __shfl_xor_sync(0xFFFFFFFF, lsum0, 1);
    lsum0 += __shfl_xor_sync(0xFFFFFFFF, lsum0, 2);
    lsum1 += __shfl_xor_sync(0xFFFFFFFF, lsum1, 1);
    lsum1 += __shfl_xor_sync(0xFFFFFFFF, lsum1, 2);
    const float inv0 = 1.0f / lsum0;
    const float inv1 = 1.0f / lsum1;
    const int row0 = warp*16 + g;
    __half* ob0 = g_ocat + (size_t)(b*NTOK + n0 + row0)*FEAT + h*DIM;
    __half* ob1 = g_ocat + (size_t)(b*NTOK + n0 + row0 + 8)*FEAT + h*DIM;
    #pragma unroll
    for (int jo = 0; jo < 16; jo++) {
        const int col = jo*8 + tg*2;
        *(__half2*)(ob0 + col) = __floats2half2_rn(oacc[jo][0]*inv0, oacc[jo][1]*inv0);
        *(__half2*)(ob1 + col) = __floats2half2_rn(oacc[jo][2]*inv1, oacc[jo][3]*inv1);
    }
}

// ============================================================
// K4: outproj split-K-8 with atomic accumulation into pre-biased out.
// grid (64, 4, 8), block 128: tile 64x64, K=128 per CTA (2 kb-iters)
// ============================================================
__global__ void outproj_atomic(const float* __restrict__ Wout,
                               float* __restrict__ out) {
    __shared__ __align__(16) char smem_raw[18432];
    __half* sA = (__half*)smem_raw;                 // 64 x 72
    __half* sB = (__half*)(smem_raw + 64*72*2);     // 64 x 72
    float*  sO = (float*)smem_raw;                  // 64 x 68 (alias after MMA)
    const int tid  = threadIdx.x;
    const int warp = tid >> 5;
    const int wr = warp >> 1, wc = warp & 1;
    const int r0 = blockIdx.x * 64, c0 = blockIdx.y * 64;
    const int k0 = blockIdx.z * 128;

    wmma::fragment<wmma::accumulator,16,16,16,float> acc[2][2];
    #pragma unroll
    for (int i = 0; i < 2; i++)
        #pragma unroll
        for (int j = 0; j < 2; j++) wmma::fill_fragment(acc[i][j], 0.0f);

    for (int kb = 0; kb < 128; kb += 64) {
        for (int idx = tid; idx < 64*8; idx += 128) {
            int r = idx >> 3, c = idx & 7;
            *(uint4*)(sA + r*72 + c*8) =
                *(const uint4*)(g_ocat + (size_t)(r0 + r)*FEAT + k0 + kb + c*8);
        }
        for (int idx = tid; idx < 64*16; idx += 128) {
            int r = idx >> 4, c = idx & 15;
            float4 t = *(const float4*)(Wout + (size_t)(k0 + kb + r)*DOUT + c0 + c*4);
            __half2* d = (__half2*)(sB + r*72 + c*4);
            d[0] = __floats2half2_rn(t.x, t.y);
            d[1] = __floats2half2_rn(t.z, t.w);
        }
        __syncthreads();
        #pragma unroll
        for (int kk = 0; kk < 4; kk++) {
            wmma::fragment<wmma::matrix_a,16,16,16,__half,wmma::row_major> fa[2];
            wmma::fragment<wmma::matrix_b,16,16,16,__half,wmma::row_major> fb[2];
            #pragma unroll
            for (int i = 0; i < 2; i++)
                wmma::load_matrix_sync(fa[i], sA + (wr*32 + i*16)*72 + kk*16, 72);
            #pragma unroll
            for (int j = 0; j < 2; j++)
                wmma::load_matrix_sync(fb[j], sB + (kk*16)*72 + wc*32 + j*16, 72);
            #pragma unroll
            for (int i = 0; i < 2; i++)
                #pragma unroll
                for (int j = 0; j < 2; j++)
                    wmma::mma_sync(acc[i][j], fa[i], fb[j], acc[i][j]);
        }
        __syncthreads();
    }
    #pragma unroll
    for (int i = 0; i < 2; i++)
        #pragma unroll
        for (int j = 0; j < 2; j++)
            wmma::store_matrix_sync(sO + (wr*32 + i*16)*68 + wc*32 + j*16,
                                    acc[i][j], 68, wmma::mem_row_major);
    __syncthreads();
    for (int idx = tid; idx < 64*64; idx += 128) {
        int r = idx >> 6, c = idx & 63;
        atomicAdd(&out[(size_t)(r0 + r)*DOUT + c0 + c], sO[r*68 + c]);
    }
}

// ============================================================
extern "C" void kernel_launch(void* const* d_in, const int* in_sizes, int n_in,
                              void* d_out, int out_size) {
    const float* X    = (const float*)d_in[0];
    const float* adj  = (const float*)d_in[1];
    const float* Wq   = (const float*)d_in[2];
    const float* bq   = (const float*)d_in[3];
    const float* Wk   = (const float*)d_in[4];
    const float* bk   = (const float*)d_in[5];
    const float* Wv   = (const float*)d_in[6];
    const float* bv   = (const float*)d_in[7];
    const float* Wout = (const float*)d_in[8];
    const float* bout = (const float*)d_in[9];
    float* out = (float*)d_out;

    const int fused_smem = 6*TB;   // 208,896 B
    cudaFuncSetAttribute(fused_attn_fa2,
                         cudaFuncAttributeMaxDynamicSharedMemorySize, fused_smem);

    adjsum_kernel<<<ADJ_GRID + BIAS_GRID, 256>>>((const float4*)adj,
                                                 (const float4*)bout, (float4*)out);
    qkv_kernel<<<dim3(BN_/64, 3*NH), 256>>>(X, Wq, bq, Wk, bk, Wv, bv);
    fused_attn_fa2<<<dim3(NTOK/128, BB*NH), 256, fused_smem>>>();
    outproj_atomic<<<dim3(BN_/64, DOUT/64, 8), 128>>>(Wout, out);
}

// round 10
// speedup vs baseline: 1.9410x; 1.0168x over previous
#include <cuda_runtime.h>
#include <cuda_fp16.h>
#include <mma.h>
#include <cstdint>

using namespace nvcuda;

#define BB    2
#define NTOK  2048
#define DIM   128
#define NH    8
#define DOUT  256
#define BN_   (BB*NTOK)            // 4096
#define FEAT  (NH*DIM)             // 1024
#define SC2E  0.03187935797f       // (1/sqrt(2048)) * log2(e)
#define LDH   136                  // fp16 tile leading dim (272 B rows)
#define LDS4  132                  // fp32 staging leading dim (qkv kernel)
#define TB    34816                // one 128 x LDH fp16 tile buffer
#define LDW   264                  // Wout smem leading dim (528 B rows)

#define ADJ_GRID  32768            // 8.39M float4 / 256
#define BIAS_GRID 1024             // 262144 float4 / 256

// ---- scratch (sanctioned __device__ globals) ----
__device__ __align__(16) __half g_adjsumh[(size_t)BB*NTOK*NTOK];    // 16.8 MB
__device__ __align__(16) __half g_q[(size_t)NH*BN_*DIM];            // 8.4 MB
__device__ __align__(16) __half g_k[(size_t)NH*BN_*DIM];
__device__ __align__(16) __half g_v[(size_t)NH*BN_*DIM];

// ---- PTX helpers ----
__device__ __forceinline__ void cp16(uint32_t saddr, const void* gptr) {
    asm volatile("cp.async.cg.shared.global [%0], [%1], 16;"
                 :: "r"(saddr), "l"(gptr));
}
#define CP_COMMIT() asm volatile("cp.async.commit_group;" ::: "memory")
#define CP_WAIT1()  asm volatile("cp.async.wait_group 1;" ::: "memory")
#define CP_WAIT0()  asm volatile("cp.async.wait_group 0;" ::: "memory")

__device__ __forceinline__ void ldsm_x4(uint32_t& r0, uint32_t& r1,
                                        uint32_t& r2, uint32_t& r3, uint32_t a) {
    asm volatile("ldmatrix.sync.aligned.m8n8.x4.shared.b16 {%0,%1,%2,%3}, [%4];"
                 : "=r"(r0), "=r"(r1), "=r"(r2), "=r"(r3) : "r"(a));
}
__device__ __forceinline__ void ldsm_x4t(uint32_t& r0, uint32_t& r1,
                                         uint32_t& r2, uint32_t& r3, uint32_t a) {
    asm volatile("ldmatrix.sync.aligned.m8n8.x4.trans.shared.b16 {%0,%1,%2,%3}, [%4];"
                 : "=r"(r0), "=r"(r1), "=r"(r2), "=r"(r3) : "r"(a));
}
__device__ __forceinline__ void mma16816(float* c, const uint32_t* a,
                                         uint32_t b0, uint32_t b1) {
    asm volatile("mma.sync.aligned.m16n8k16.row.col.f32.f16.f16.f32 "
                 "{%0,%1,%2,%3}, {%4,%5,%6,%7}, {%8,%9}, {%0,%1,%2,%3};"
                 : "+f"(c[0]), "+f"(c[1]), "+f"(c[2]), "+f"(c[3])
                 : "r"(a[0]), "r"(a[1]), "r"(a[2]), "r"(a[3]), "r"(b0), "r"(b1));
}
__device__ __forceinline__ float ex2f(float x) {
    float y;
    asm("ex2.approx.ftz.f32 %0, %1;" : "=f"(y) : "f"(x));
    return y;
}

// ============================================================
// K1: blocks [0, ADJ_GRID): adjsumh = fp16(sum_w adj);
//     blocks [ADJ_GRID, +BIAS_GRID): out = bias broadcast (pre-init for atomics)
// ============================================================
__global__ void adjsum_kernel(const float4* __restrict__ adj,
                              const float4* __restrict__ bout4,
                              float4* __restrict__ out4) {
    const int tid = threadIdx.x;
    if (blockIdx.x < ADJ_GRID) {
        size_t i = (size_t)blockIdx.x * 256 + tid;
        float4 t = adj[i];
        g_adjsumh[i] = __float2half_rn((t.x + t.y) + (t.z + t.w));
    } else {
        size_t j = (size_t)(blockIdx.x - ADJ_GRID) * 256 + tid;
        out4[j] = bout4[j & 63];
    }
}

// ============================================================
// K2: q/k/v[h] = fp16( X @ W[h] + b[h] )   (unchanged, proven)
// ============================================================
__global__ void qkv_kernel(const float* __restrict__ X,
                           const float* __restrict__ Wq, const float* __restrict__ bq,
                           const float* __restrict__ Wk, const float* __restrict__ bk,
                           const float* __restrict__ Wv, const float* __restrict__ bv) {
    __shared__ __align__(16) char smem_raw[17408 + TB];
    __half* sA = (__half*)smem_raw;
    __half* sB = (__half*)(smem_raw + 17408);
    float*  sO = (float*)(smem_raw + 17408);
    const int tid  = threadIdx.x;
    const int warp = tid >> 5;
    const int wr = warp >> 2, wc = warp & 3;
    const int row0 = blockIdx.x * 64;
    const int z = blockIdx.y;
    const int mat = z >> 3, h = z & 7;

    const float* Wm = (mat == 0 ? Wq : (mat == 1 ? Wk : Wv)) + (size_t)h*DIM*DIM;
    const float* bm = (mat == 0 ? bq : (mat == 1 ? bk : bv)) + (size_t)h*DIM;
    __half* outp = (mat == 0 ? g_q : (mat == 1 ? g_k : g_v)) + (size_t)h*BN_*DIM;

    for (int idx = tid; idx < 64*32; idx += 256) {
        int r = idx >> 5, c = idx & 31;
        float4 t = *(const float4*)(X + (size_t)(row0 + r)*DIM + c*4);
        __half2* d = (__half2*)(sA + r*LDH + c*4);
        d[0] = __floats2half2_rn(t.x, t.y);
        d[1] = __floats2half2_rn(t.z, t.w);
    }
    for (int idx = tid; idx < 128*32; idx += 256) {
        int r = idx >> 5, c = idx & 31;
        float4 t = *(const float4*)(Wm + (size_t)r*DIM + c*4);
        __half2* d = (__half2*)(sB + r*LDH + c*4);
        d[0] = __floats2half2_rn(t.x, t.y);
        d[1] = __floats2half2_rn(t.z, t.w);
    }
    __syncthreads();

    wmma::fragment<wmma::accumulator,16,16,16,float> acc[2][2];
    #pragma unroll
    for (int i = 0; i < 2; i++)
        #pragma unroll
        for (int j = 0; j < 2; j++) wmma::fill_fragment(acc[i][j], 0.0f);

    #pragma unroll
    for (int k = 0; k < 8; k++) {
        wmma::fragment<wmma::matrix_a,16,16,16,__half,wmma::row_major> fa[2];
        wmma::fragment<wmma::matrix_b,16,16,16,__half,wmma::row_major> fb[2];
        #pragma unroll
        for (int i = 0; i < 2; i++)
            wmma::load_matrix_sync(fa[i], sA + (wr*32 + i*16)*LDH + k*16, LDH);
        #pragma unroll
        for (int j = 0; j < 2; j++)
            wmma::load_matrix_sync(fb[j], sB + (k*16)*LDH + wc*32 + j*16, LDH);
        #pragma unroll
        for (int i = 0; i < 2; i++)
            #pragma unroll
            for (int j = 0; j < 2; j++)
                wmma::mma_sync(acc[i][j], fa[i], fb[j], acc[i][j]);
    }
    __syncthreads();
    #pragma unroll
    for (int i = 0; i < 2; i++)
        #pragma unroll
        for (int j = 0; j < 2; j++)
            wmma::store_matrix_sync(sO + (wr*32 + i*16)*LDS4 + wc*32 + j*16,
                                    acc[i][j], LDS4, wmma::mem_row_major);
    __syncthreads();
    for (int idx = tid; idx < 64*128; idx += 256) {
        int r = idx >> 7, e = idx & 127;
        outp[(size_t)(row0 + r)*DIM + e] = __float2half_rn(sO[r*LDS4 + e] + bm[e]);
    }
}

// ============================================================
// K3 (FUSED FA2 + output projection epilogue):
//   mainloop unchanged (proven). Epilogue: normalized O repacked as A-frags
//   (c->a identity), Wout slice staged fp16 in smem, 16x256 GEMM per warp,
//   atomicAdd into pre-biased out.
// ============================================================
__global__ __launch_bounds__(256, 1) void fused_attn_fa2(
        const float* __restrict__ Wout, float* __restrict__ out) {
    extern __shared__ __align__(16) char dsm[];
    const uint32_t uBase = (uint32_t)__cvta_generic_to_shared(dsm);

    const int tid  = threadIdx.x;
    const int warp = tid >> 5;
    const int lane = tid & 31;
    const int g    = lane >> 2;
    const int tg   = lane & 3;
    const int n0 = blockIdx.x * 128;
    const int b = blockIdx.y >> 3, h = blockIdx.y & 7;

    const __half* qp  = g_q + (size_t)h*BN_*DIM + (size_t)b*NTOK*DIM;
    const __half* kp  = g_k + (size_t)h*BN_*DIM + (size_t)b*NTOK*DIM;
    const __half* vp  = g_v + (size_t)h*BN_*DIM + (size_t)b*NTOK*DIM;
    const __half* adjp = g_adjsumh + (size_t)b*NTOK*NTOK + (size_t)n0*NTOK;

    const int lrow_a = ((lane >> 3) & 1)*8 + (lane & 7);
    const int lcol_a = (lane >> 4)*8;
    const int lrow_b = ((lane >> 4) & 1)*8 + (lane & 7);
    const int lcol_b = ((lane >> 3) & 1)*8;

    // ---- prologue: stage Q through smem, extract a-frags ----
    for (int idx = tid; idx < 128*16; idx += 256) {
        int r = idx >> 4, c = idx & 15;
        *(uint4*)(dsm + r*272 + c*16) = *(const uint4*)(qp + (size_t)(n0 + r)*DIM + c*8);
    }
    __syncthreads();
    uint32_t aQ[8][4];
    #pragma unroll
    for (int kk = 0; kk < 8; kk++) {
        uint32_t a = uBase + (uint32_t)(warp*16 + lrow_a)*272 + (kk*16 + lcol_a)*2;
        ldsm_x4(aQ[kk][0], aQ[kk][1], aQ[kk][2], aQ[kk][3], a);
    }
    __syncthreads();

    #pragma unroll
    for (int j = 0; j < 2; j++) {
        const uint32_t uK = uBase + j*TB, uV = uBase + (2 + j)*TB, uA = uBase + (4 + j)*TB;
        const int m0 = j*128;
        for (int idx = tid; idx < 128*16; idx += 256) {
            int r = idx >> 4, c = idx & 15;
            cp16(uK + r*272 + c*16, kp + (size_t)(m0 + r)*DIM + c*8);
        }
        for (int idx = tid; idx < 128*16; idx += 256) {
            int r = idx >> 4, c = idx & 15;
            cp16(uV + r*272 + c*16, vp + (size_t)(m0 + r)*DIM + c*8);
        }
        for (int idx = tid; idx < 128*16; idx += 256) {
            int r = idx >> 4, c = idx & 15;
            cp16(uA + r*272 + c*16, adjp + (size_t)r*NTOK + m0 + c*8);
        }
        CP_COMMIT();
    }

    float oacc[16][4];
    #pragma unroll
    for (int j = 0; j < 16; j++)
        #pragma unroll
        for (int e = 0; e < 4; e++) oacc[j][e] = 0.f;
    float lsum0 = 0.f, lsum1 = 0.f;

    for (int it = 0; it < 16; it++) {
        const int bi = it & 1;
        const uint32_t uK = uBase + bi*TB;
        const uint32_t uV = uBase + (2 + bi)*TB;
        const __half* sAdj = (const __half*)(dsm + (size_t)(4 + bi)*TB);

        if (it < 15) { CP_WAIT1(); } else { CP_WAIT0(); }
        __syncthreads();

        // ---- S = Q K^T ----
        float sacc[16][4];
        #pragma unroll
        for (int j = 0; j < 16; j++)
            #pragma unroll
            for (int e = 0; e < 4; e++) sacc[j][e] = 0.f;
        #pragma unroll
        for (int kk = 0; kk < 8; kk++) {
            #pragma unroll
            for (int jjp = 0; jjp < 8; jjp++) {
                uint32_t r0, r1, r2, r3;
                ldsm_x4(r0, r1, r2, r3,
                        uK + (uint32_t)(jjp*16 + lrow_b)*272 + (kk*16 + lcol_b)*2);
                mma16816(sacc[2*jjp],     aQ[kk], r0, r1);
                mma16816(sacc[2*jjp + 1], aQ[kk], r2, r3);
            }
        }

        // ---- exp in registers (ex2 with folded scale) ----
        uint32_t aP[8][4];
        const int row0 = warp*16 + g;
        #pragma unroll
        for (int jj = 0; jj < 16; jj++) {
            const int col = jj*8 + tg*2;
            float2 a0 = __half22float2(*(const __half2*)(sAdj + row0*LDH + col));
            float2 a1 = __half22float2(*(const __half2*)(sAdj + (row0 + 8)*LDH + col));
            float e00 = ex2f(sacc[jj][0] * SC2E * a0.x);
            float e01 = ex2f(sacc[jj][1] * SC2E * a0.y);
            float e10 = ex2f(sacc[jj][2] * SC2E * a1.x);
            float e11 = ex2f(sacc[jj][3] * SC2E * a1.y);
            lsum0 += e00 + e01;
            lsum1 += e10 + e11;
            __half2 p0 = __floats2half2_rn(e00, e01);
            __half2 p1 = __floats2half2_rn(e10, e11);
            aP[jj >> 1][(jj & 1)*2 + 0] = *(uint32_t*)&p0;
            aP[jj >> 1][(jj & 1)*2 + 1] = *(uint32_t*)&p1;
        }

        // ---- O += P @ V ----
        #pragma unroll
        for (int kk = 0; kk < 8; kk++) {
            #pragma unroll
            for (int jop = 0; jop < 8; jop++) {
                uint32_t r0, r1, r2, r3;
                ldsm_x4t(r0, r1, r2, r3,
                         uV + (uint32_t)(kk*16 + lrow_a)*272 + (jop*16 + lcol_a)*2);
                mma16816(oacc[2*jop],     aP[kk], r0, r1);
                mma16816(oacc[2*jop + 1], aP[kk], r2, r3);
            }
        }
        __syncthreads();

        if (it + 2 < 16) {
            const int m2 = (it + 2)*128;
            for (int idx = tid; idx < 128*16; idx += 256) {
                int r = idx >> 4, c = idx & 15;
                cp16(uK + r*272 + c*16, kp + (size_t)(m2 + r)*DIM + c*8);
            }
            for (int idx = tid; idx < 128*16; idx += 256) {
                int r = idx >> 4, c = idx & 15;
                cp16(uV + r*272 + c*16, vp + (size_t)(m2 + r)*DIM + c*8);
            }
            const uint32_t uA = uBase + (4 + bi)*TB;
            for (int idx = tid; idx < 128*16; idx += 256) {
                int r = idx >> 4, c = idx & 15;
                cp16(uA + r*272 + c*16, adjp + (size_t)r*NTOK + m2 + c*8);
            }
            CP_COMMIT();
        }
    }

    // ---- epilogue 1: row sums -> normalized O as A-frags (c->a identity) ----
    lsum0 += __shfl_xor_sync(0xFFFFFFFF, lsum0, 1);
    lsum0 += __shfl_xor_sync(0xFFFFFFFF, lsum0, 2);
    lsum1 += __shfl_xor_sync(0xFFFFFFFF, lsum1, 1);
    lsum1 += __shfl_xor_sync(0xFFFFFFFF, lsum1, 2);
    const float inv0 = 1.0f / lsum0;
    const float inv1 = 1.0f / lsum1;
    uint32_t aO[8][4];
    #pragma unroll
    for (int kk = 0; kk < 8; kk++) {
        __half2 p;
        p = __floats2half2_rn(oacc[2*kk][0]*inv0,   oacc[2*kk][1]*inv0);
        aO[kk][0] = *(uint32_t*)&p;
        p = __floats2half2_rn(oacc[2*kk][2]*inv1,   oacc[2*kk][3]*inv1);
        aO[kk][1] = *(uint32_t*)&p;
        p = __floats2half2_rn(oacc[2*kk+1][0]*inv0, oacc[2*kk+1][1]*inv0);
        aO[kk][2] = *(uint32_t*)&p;
        p = __floats2half2_rn(oacc[2*kk+1][2]*inv1, oacc[2*kk+1][3]*inv1);
        aO[kk][3] = *(uint32_t*)&p;
    }

    // ---- epilogue 2: stage Wout slice [h*128 .. +128) x 256 as fp16 ----
    // (mainloop buffers are dead; loop's final __syncthreads covers reuse)
    const float* wsl = Wout + (size_t)(h*DIM)*DOUT;
    for (int idx = tid; idx < 128*64; idx += 256) {
        int r = idx >> 6, c4 = idx & 63;
        float4 t = *(const float4*)(wsl + (size_t)r*DOUT + c4*4);
        __half2* d = (__half2*)((__half*)dsm + r*LDW + c4*4);
        d[0] = __floats2half2_rn(t.x, t.y);
        d[1] = __floats2half2_rn(t.z, t.w);
    }
    __syncthreads();

    // ---- epilogue 3: out_tile(16x256) = O_norm(16x128) @ Wout_slice ----
    float outacc[32][4];
    #pragma unroll
    for (int j = 0; j < 32; j++)
        #pragma unroll
        for (int e = 0; e < 4; e++) outacc[j][e] = 0.f;
    #pragma unroll
    for (int kk = 0; kk < 8; kk++) {
        #pragma unroll
        for (int jop = 0; jop < 16; jop++) {
            uint32_t r0, r1, r2, r3;
            ldsm_x4t(r0, r1, r2, r3,
                     uBase + (uint32_t)(kk*16 + lrow_a)*(LDW*2) + (jop*16 + lcol_a)*2);
            mma16816(outacc[2*jop],     aO[kk], r0, r1);
            mma16816(outacc[2*jop + 1], aO[kk], r2, r3);
        }
    }

    // ---- epilogue 4: atomicAdd into pre-biased out ----
    const int orow = b*NTOK + n0 + warp*16 + g;
    float* o0 = out + (size_t)orow*DOUT;
    float* o1 = o0 + 8*DOUT;
    #pragma unroll
    for (int jt = 0; jt < 32; jt++) {
        const int col = jt*8 + tg*2;
        atomicAdd(o0 + col,     outacc[jt][0]);
        atomicAdd(o0 + col + 1, outacc[jt][1]);
        atomicAdd(o1 + col,     outacc[jt][2]);
        atomicAdd(o1 + col + 1, outacc[jt][3]);
    }
}

// ============================================================
extern "C" void kernel_launch(void* const* d_in, const int* in_sizes, int n_in,
                              void* d_out, int out_size) {
    const float* X    = (const float*)d_in[0];
    const float* adj  = (const float*)d_in[1];
    const float* Wq   = (const float*)d_in[2];
    const float* bq   = (const float*)d_in[3];
    const float* Wk   = (const float*)d_in[4];
    const float* bk   = (const float*)d_in[5];
    const float* Wv   = (const float*)d_in[6];
    const float* bv   = (const float*)d_in[7];
    const float* Wout = (const float*)d_in[8];
    const float* bout = (const float*)d_in[9];
    float* out = (float*)d_out;

    const int fused_smem = 6*TB;   // 208,896 B (epilogue reuse: 67,584 B for Wout)
    cudaFuncSetAttribute(fused_attn_fa2,
                         cudaFuncAttributeMaxDynamicSharedMemorySize, fused_smem);

    adjsum_kernel<<<ADJ_GRID + BIAS_GRID, 256>>>((const float4*)adj,
                                                 (const float4*)bout, (float4*)out);
    qkv_kernel<<<dim3(BN_/64, 3*NH), 256>>>(X, Wq, bq, Wk, bk, Wv, bv);
    fused_attn_fa2<<<dim3(NTOK/128, BB*NH), 256, fused_smem>>>(Wout, out);
}